// round 5
// baseline (speedup 1.0000x reference)
#include <cuda_runtime.h>
#include <cstdint>

#define R  5
#define E  50000
#define NN 20000      // NU == NI
#define NF 4
#define DN 16
#define DR 64
#define DO 64
// TAU = 0.5 -> 1/TAU = 2.0f

// ---------------- scratch (device globals; no allocation) ----------------
__device__ __align__(16) float g_blended[R * E];
__device__ __align__(16) float g_w[R * E];
__device__ float g_norm_u[NN];
__device__ float g_norm_i[NN];
__device__ int   g_deg[2 * NN];
__device__ int   g_off[2 * NN];
__device__ int   g_cur[2 * NN];
__device__ int   g_adj[2 * R * E];            // [side][R*E]
__device__ __align__(16) float g_hu[R * NN * DN];
__device__ __align__(16) float g_hi[R * NN * DN];
__device__ __align__(16) float g_rfw[(size_t)R * E * DN];   // per-edge rf_k @ Wf^T
__device__ __align__(16) float g_rfr[(size_t)R * E * DN];   // per-edge rf_k @ Wr^T

__device__ __forceinline__ float dot4(float4 a, float4 b) {
    return a.x * b.x + a.y * b.y + a.z * b.z + a.w * b.w;
}

// reduce-scatter of 16 floats over an 8-lane group (static indices only).
// On exit, lane sub owns outputs {2*sub, 2*sub+1} in v[0], v[1].
__device__ __forceinline__ void rs8(float* v, int sub) {
#pragma unroll
    for (int i = 0; i < 8; i++) {
        float send = (sub & 4) ? v[i] : v[i + 8];
        float got  = __shfl_xor_sync(0xffffffffu, send, 4);
        float keep = (sub & 4) ? v[i + 8] : v[i];
        v[i] = keep + got;
    }
#pragma unroll
    for (int i = 0; i < 4; i++) {
        float send = (sub & 2) ? v[i] : v[i + 4];
        float got  = __shfl_xor_sync(0xffffffffu, send, 2);
        float keep = (sub & 2) ? v[i + 4] : v[i];
        v[i] = keep + got;
    }
#pragma unroll
    for (int i = 0; i < 2; i++) {
        float send = (sub & 1) ? v[i] : v[i + 2];
        float got  = __shfl_xor_sync(0xffffffffu, send, 1);
        float keep = (sub & 1) ? v[i + 2] : v[i];
        v[i] = keep + got;
    }
}

// ---------------- kernel 1: zero counters ----------------
__global__ void zero_kernel() {
    int i = blockIdx.x * blockDim.x + threadIdx.x;
    if (i < NN) {
        g_norm_u[i] = 0.f;
        g_norm_i[i] = 0.f;
        g_deg[i] = 0;
        g_deg[NN + i] = 0;
    }
}

// ---------------- kernel 2: hu = uh @ Wfwd^T, hi = ih @ Wrev^T ----------------
__global__ void proj_kernel(const float* __restrict__ user_h,
                            const float* __restrict__ item_h,
                            const float* __restrict__ w_fwd,
                            const float* __restrict__ w_rev,
                            const int* __restrict__ kptr) {
    int idx = blockIdx.x * blockDim.x + threadIdx.x;
    if (idx >= R * NN) return;
    int side = blockIdx.y;
    int r = idx / NN, n = idx % NN;
    int kk = *kptr;

    const float* h = (side ? item_h : user_h) + ((size_t)(kk * R + r) * NN + n) * DN;
    const float* W = (side ? w_rev : w_fwd) + r * DN * DN;
    float* out = (side ? g_hi : g_hu) + ((size_t)r * NN + n) * DN;

    float x[DN];
#pragma unroll
    for (int i = 0; i < 4; i++) {
        float4 t = reinterpret_cast<const float4*>(h)[i];
        x[4*i+0] = t.x; x[4*i+1] = t.y; x[4*i+2] = t.z; x[4*i+3] = t.w;
    }
#pragma unroll
    for (int o = 0; o < DN; o++) {
        float acc = 0.f;
#pragma unroll
        for (int d = 0; d < DN; d++) acc += x[d] * __ldg(&W[o * DN + d]);
        out[o] = acc;
    }
}

// ---------------- kernel 3: blend (4 edges/warp, 8 lanes/edge) ----------------
// Computes blended weight + deg histogram + per-edge rfw/rfr projections.
__global__ void blend_kernel(const float* __restrict__ user_h,
                             const float* __restrict__ item_h,
                             const float* __restrict__ user_hsum,
                             const float* __restrict__ item_hsum,
                             const float* __restrict__ review_feat,
                             const float* __restrict__ prototypes,
                             const float* __restrict__ eta,
                             const float* __restrict__ rw_fwd,
                             const float* __restrict__ rw_rev,
                             const int* __restrict__ edge_src,
                             const int* __restrict__ edge_dst,
                             const int* __restrict__ kptr) {
    __shared__ float4 sproto[NF * DR / 4];   // 64
    __shared__ float4 sWf[DN * DR / 4];      // 256
    __shared__ float4 sWr[DN * DR / 4];      // 256
    int tid = threadIdx.x;
    int r = blockIdx.y;
    {
        const float4* p4  = reinterpret_cast<const float4*>(prototypes);
        const float4* wf4 = reinterpret_cast<const float4*>(rw_fwd + r * DN * DR);
        const float4* wr4 = reinterpret_cast<const float4*>(rw_rev + r * DN * DR);
        for (int i = tid; i < 576; i += 256) {
            if (i < 64)       sproto[i] = p4[i];
            else if (i < 320) sWf[i - 64] = wf4[i - 64];
            else              sWr[i - 320] = wr4[i - 320];
        }
    }
    __syncthreads();

    int warp = tid >> 5, lane = tid & 31, g = lane >> 3, sub = lane & 7;
    int e = (blockIdx.x * 8 + warp) * 4 + g;
    bool valid = e < E;
    int ec = valid ? e : E - 1;
    int kk = *kptr;
    int id = r * E + ec;
    int src = edge_src[id];
    int dst = edge_dst[id];

    // ---- stream rf row (256 floats), anchor partials ----
    const float4* rf4 = reinterpret_cast<const float4*>(review_feat + (size_t)id * (NF * DR));
    float4 q[8];
    float af[4] = {0.f, 0.f, 0.f, 0.f};
#pragma unroll
    for (int j = 0; j < 8; j++) {
        q[j] = rf4[sub + 8 * j];
        af[j >> 1] += dot4(q[j], sproto[sub + 8 * j]);
    }
#pragma unroll
    for (int o = 1; o < 8; o <<= 1) {
        af[0] += __shfl_xor_sync(0xffffffffu, af[0], o);
        af[1] += __shfl_xor_sync(0xffffffffu, af[1], o);
        af[2] += __shfl_xor_sync(0xffffffffu, af[2], o);
        af[3] += __shfl_xor_sync(0xffffffffu, af[3], o);
    }

    // ---- sim_all denominator (hsum, 64 floats each side) ----
    const float4* ra = reinterpret_cast<const float4*>(user_hsum + ((size_t)r * NN + src) * (NF * DN));
    const float4* ca = reinterpret_cast<const float4*>(item_hsum + ((size_t)r * NN + dst) * (NF * DN));
    float p = dot4(ra[2 * sub], ca[2 * sub]) + dot4(ra[2 * sub + 1], ca[2 * sub + 1]);
    p += __shfl_xor_sync(0xffffffffu, p, 1);         // full dot for f = sub/2
    float ex = __expf(2.f * p);
    ex += __shfl_xor_sync(0xffffffffu, ex, 2);
    ex += __shfl_xor_sync(0xffffffffu, ex, 4);
    float denom_sim = ex;                            // each f counted once

    // ---- cosine sim (lanes sub<4 of each group) ----
    float uu = 0.f, vv = 0.f, uv = 0.f;
    if (sub < 4) {
        float4 a = reinterpret_cast<const float4*>(user_h + ((size_t)(kk * R + r) * NN + src) * DN)[sub];
        float4 b = reinterpret_cast<const float4*>(item_h + ((size_t)(kk * R + r) * NN + dst) * DN)[sub];
        uu = dot4(a, a); vv = dot4(b, b); uv = dot4(a, b);
    }
    uu += __shfl_xor_sync(0xffffffffu, uu, 1); uu += __shfl_xor_sync(0xffffffffu, uu, 2);
    vv += __shfl_xor_sync(0xffffffffu, vv, 1); vv += __shfl_xor_sync(0xffffffffu, vv, 2);
    uv += __shfl_xor_sync(0xffffffffu, uv, 1); uv += __shfl_xor_sync(0xffffffffu, uv, 2);

    // ---- rf_k matvec against Wf, Wr (partials over this lane's 8 floats) ----
    float4 xa = q[0], xb = q[1];
#pragma unroll
    for (int j = 0; j < 8; j++) {
        if (j == 2 * kk)     xa = q[j];
        if (j == 2 * kk + 1) xb = q[j];
    }
    float vf[16], vr[16];
#pragma unroll
    for (int o = 0; o < 16; o++) {
        vf[o] = dot4(xa, sWf[o * 16 + sub]) + dot4(xb, sWf[o * 16 + 8 + sub]);
        vr[o] = dot4(xa, sWr[o * 16 + sub]) + dot4(xb, sWr[o * 16 + 8 + sub]);
    }
    rs8(vf, sub);
    rs8(vr, sub);
    if (valid) {
        reinterpret_cast<float2*>(g_rfw)[(size_t)id * 8 + sub] = make_float2(vf[0], vf[1]);
        reinterpret_cast<float2*>(g_rfr)[(size_t)id * 8 + sub] = make_float2(vr[0], vr[1]);
    }

    // ---- blended weight (lane sub==0 of each group) ----
    if (sub == 0 && valid) {
        float nu = fmaxf(sqrtf(uu), 1e-12f);
        float nv = fmaxf(sqrtf(vv), 1e-12f);
        float sim_k = 2.f * uv / (nu * nv);
        float exp_sim = __expf(sim_k) / denom_sim;

        float a0 = 2.f * af[0], a1 = 2.f * af[1], a2 = 2.f * af[2], a3 = 2.f * af[3];
        float denom_a = __expf(a0) + __expf(a1) + __expf(a2) + __expf(a3);
        float ak = (kk == 0) ? a0 : (kk == 1) ? a1 : (kk == 2) ? a2 : a3;
        float exp_anchor = __expf(ak) / denom_a;

        float gs = 1.f / (1.f + __expf(-eta[id]));
        float bl = gs * exp_anchor + (1.f - gs) * exp_sim;

        g_blended[id] = bl;
        atomicAdd(&g_norm_u[src], bl);
        atomicAdd(&g_norm_i[dst], bl);
        atomicAdd(&g_deg[src], 1);
        atomicAdd(&g_deg[NN + dst], 1);
    }
}

// ---------------- kernel 4: exclusive scan of degrees -> CSR offsets ----------------
__global__ void scan_kernel() {
    int side = blockIdx.x;           // 0 users, 1 items
    int t = threadIdx.x;             // 1024
    const int* deg = g_deg + side * NN;
    int* off = g_off + side * NN;
    int* cur = g_cur + side * NN;
    __shared__ int part[1024];

    int base = t * 20;               // 1024*20 >= 20000
    int s = 0;
#pragma unroll
    for (int i = 0; i < 20; i++) {
        int idx = base + i;
        if (idx < NN) s += deg[idx];
    }
    part[t] = s;
    __syncthreads();
    for (int o = 1; o < 1024; o <<= 1) {
        int v = 0;
        if (t >= o) v = part[t - o];
        __syncthreads();
        if (t >= o) part[t] += v;
        __syncthreads();
    }
    int run = (t == 0) ? 0 : part[t - 1];
#pragma unroll
    for (int i = 0; i < 20; i++) {
        int idx = base + i;
        if (idx < NN) {
            off[idx] = run;
            cur[idx] = run;
            run += deg[idx];
        }
    }
}

// ---------------- kernel 5: normalized weight + adjacency fill ----------------
__global__ void fill_kernel(const int* __restrict__ edge_src,
                            const int* __restrict__ edge_dst,
                            float* __restrict__ out_int_dist) {
    int r = blockIdx.y;
    int e = blockIdx.x * blockDim.x + threadIdx.x;
    if (e >= E) return;
    int id = r * E + e;
    int src = edge_src[id];
    int dst = edge_dst[id];
    float bl = g_blended[id];
    float w = bl * rsqrtf(g_norm_u[src] * g_norm_i[dst]);
    g_w[id] = w;
    out_int_dist[id] = w;
    int su = atomicAdd(&g_cur[src], 1);
    g_adj[su] = id;
    int si = atomicAdd(&g_cur[NN + dst], 1);
    g_adj[R * E + si] = id;
}

// ---------------- kernel 6: gather messages + leaky_relu + FC (fused) ----------------
__global__ void gather_kernel(const int* __restrict__ edge_src,
                              const int* __restrict__ edge_dst,
                              const float* __restrict__ ufc_w, const float* __restrict__ ufc_b,
                              const float* __restrict__ ifc_w, const float* __restrict__ ifc_b,
                              float* __restrict__ out) {
    __shared__ float4 sW[DO * DN / 4];   // 256 float4 = 4KB
    __shared__ float  sB[DO];
    int side = blockIdx.y;               // 0 users, 1 items
    int tid = threadIdx.x;
    {
        const float4* W4 = reinterpret_cast<const float4*>(side ? ifc_w : ufc_w);
        const float* B = side ? ifc_b : ufc_b;
        for (int i = tid; i < DO * DN / 4; i += 256) sW[i] = W4[i];
        if (tid < DO) sB[tid] = B[tid];
    }
    __syncthreads();

    int n = blockIdx.x * 256 + tid;
    if (n >= NN) return;

    int start = g_off[side * NN + n];
    int deg = g_deg[side * NN + n];
    const int* adj = g_adj + (size_t)side * R * E;
    const float* hsrc = side ? g_hu : g_hi;            // item side gathers hu[src]; user side hi[dst]
    const float* rp   = side ? g_rfw : g_rfr;
    const int* partner_arr = side ? edge_src : edge_dst;

    float4 m0 = make_float4(0,0,0,0), m1 = m0, m2 = m0, m3 = m0;
    for (int s = 0; s < deg; s++) {
        int id = adj[start + s];
        int r = id / E;
        int partner = partner_arr[id];
        float w = g_w[id];
        const float4* h4 = reinterpret_cast<const float4*>(hsrc + ((size_t)r * NN + partner) * DN);
        const float4* p4 = reinterpret_cast<const float4*>(rp + (size_t)id * DN);
        float4 a, b;
        a = h4[0]; b = p4[0]; m0.x += w*(a.x+b.x); m0.y += w*(a.y+b.y); m0.z += w*(a.z+b.z); m0.w += w*(a.w+b.w);
        a = h4[1]; b = p4[1]; m1.x += w*(a.x+b.x); m1.y += w*(a.y+b.y); m1.z += w*(a.z+b.z); m1.w += w*(a.w+b.w);
        a = h4[2]; b = p4[2]; m2.x += w*(a.x+b.x); m2.y += w*(a.y+b.y); m2.z += w*(a.z+b.z); m2.w += w*(a.w+b.w);
        a = h4[3]; b = p4[3]; m3.x += w*(a.x+b.x); m3.y += w*(a.y+b.y); m3.z += w*(a.z+b.z); m3.w += w*(a.w+b.w);
    }

    // leaky relu
    float4 mv[4] = {m0, m1, m2, m3};
#pragma unroll
    for (int i = 0; i < 4; i++) {
        mv[i].x = mv[i].x >= 0.f ? mv[i].x : 0.1f * mv[i].x;
        mv[i].y = mv[i].y >= 0.f ? mv[i].y : 0.1f * mv[i].y;
        mv[i].z = mv[i].z >= 0.f ? mv[i].z : 0.1f * mv[i].z;
        mv[i].w = mv[i].w >= 0.f ? mv[i].w : 0.1f * mv[i].w;
    }

    float* outp = out + (size_t)side * NN * DO + (size_t)n * DO;
#pragma unroll
    for (int ob = 0; ob < 16; ob++) {
        float4 ov;
        int o0 = 4 * ob;
        ov.x = sB[o0+0] + dot4(mv[0], sW[(o0+0)*4+0]) + dot4(mv[1], sW[(o0+0)*4+1])
                        + dot4(mv[2], sW[(o0+0)*4+2]) + dot4(mv[3], sW[(o0+0)*4+3]);
        ov.y = sB[o0+1] + dot4(mv[0], sW[(o0+1)*4+0]) + dot4(mv[1], sW[(o0+1)*4+1])
                        + dot4(mv[2], sW[(o0+1)*4+2]) + dot4(mv[3], sW[(o0+1)*4+3]);
        ov.z = sB[o0+2] + dot4(mv[0], sW[(o0+2)*4+0]) + dot4(mv[1], sW[(o0+2)*4+1])
                        + dot4(mv[2], sW[(o0+2)*4+2]) + dot4(mv[3], sW[(o0+2)*4+3]);
        ov.w = sB[o0+3] + dot4(mv[0], sW[(o0+3)*4+0]) + dot4(mv[1], sW[(o0+3)*4+1])
                        + dot4(mv[2], sW[(o0+3)*4+2]) + dot4(mv[3], sW[(o0+3)*4+3]);
        reinterpret_cast<float4*>(outp)[ob] = ov;
    }
}

// ---------------- launch ----------------
extern "C" void kernel_launch(void* const* d_in, const int* in_sizes, int n_in,
                              void* d_out, int out_size) {
    const float* user_h      = (const float*)d_in[0];
    const float* item_h      = (const float*)d_in[1];
    const float* user_hsum   = (const float*)d_in[2];
    const float* item_hsum   = (const float*)d_in[3];
    const float* review_feat = (const float*)d_in[4];
    const float* prototypes  = (const float*)d_in[5];
    const float* eta         = (const float*)d_in[6];
    const float* node_w_fwd  = (const float*)d_in[7];
    const float* review_w_fwd= (const float*)d_in[8];
    const float* node_w_rev  = (const float*)d_in[9];
    const float* review_w_rev= (const float*)d_in[10];
    const float* ufc_w       = (const float*)d_in[11];
    const float* ufc_b       = (const float*)d_in[12];
    const float* ifc_w       = (const float*)d_in[13];
    const float* ifc_b       = (const float*)d_in[14];
    const int*   edge_src    = (const int*)d_in[15];
    const int*   edge_dst    = (const int*)d_in[16];
    const int*   kptr        = (const int*)d_in[17];

    float* out = (float*)d_out;
    float* out_int = out + (size_t)2 * NN * DO;   // int_dist after ufeat+ifeat

    zero_kernel<<<(NN + 255) / 256, 256>>>();

    dim3 gp((R * NN + 255) / 256, 2);
    proj_kernel<<<gp, 256>>>(user_h, item_h, node_w_fwd, node_w_rev, kptr);

    dim3 gb((E + 31) / 32, R);   // 32 edges per 256-thread block
    blend_kernel<<<gb, 256>>>(user_h, item_h, user_hsum, item_hsum,
                              review_feat, prototypes, eta,
                              review_w_fwd, review_w_rev,
                              edge_src, edge_dst, kptr);

    scan_kernel<<<2, 1024>>>();

    dim3 gf((E + 255) / 256, R);
    fill_kernel<<<gf, 256>>>(edge_src, edge_dst, out_int);

    dim3 gg((NN + 255) / 256, 2);
    gather_kernel<<<gg, 256>>>(edge_src, edge_dst, ufc_w, ufc_b, ifc_w, ifc_b, out);
}

// round 6
// speedup vs baseline: 1.0980x; 1.0980x over previous
#include <cuda_runtime.h>
#include <cstdint>

#define R  5
#define E  50000
#define NN 20000      // NU == NI
#define NF 4
#define DN 16
#define DR 64
#define DO 64
// TAU = 0.5 -> 1/TAU = 2.0f

// ---------------- scratch (device globals; no allocation) ----------------
__device__ __align__(16) float g_blended[R * E];
__device__ __align__(16) float g_norm_u[NN];
__device__ __align__(16) float g_norm_i[NN];
__device__ __align__(16) float g_hu[R * NN * DN];
__device__ __align__(16) float g_hi[R * NN * DN];
__device__ __align__(16) float g_user_msg[NN * DN];
__device__ __align__(16) float g_item_msg[NN * DN];
__device__ __align__(16) float g_rfw[(size_t)R * E * DN];   // per-edge rf_k @ Wf^T
__device__ __align__(16) float g_rfr[(size_t)R * E * DN];   // per-edge rf_k @ Wr^T

__device__ __forceinline__ float dot4(float4 a, float4 b) {
    return a.x * b.x + a.y * b.y + a.z * b.z + a.w * b.w;
}

// vector global reduction (sm_90+): 4 floats in one RED
__device__ __forceinline__ void red_add_v4(float* p, float4 m) {
    asm volatile("red.global.add.v4.f32 [%0], {%1, %2, %3, %4};"
                 :: "l"(p), "f"(m.x), "f"(m.y), "f"(m.z), "f"(m.w)
                 : "memory");
}

// reduce-scatter of 16 floats over an 8-lane group (static indices only).
// On exit, lane sub owns outputs {2*sub, 2*sub+1} in v[0], v[1].
__device__ __forceinline__ void rs8(float* v, int sub) {
#pragma unroll
    for (int i = 0; i < 8; i++) {
        float send = (sub & 4) ? v[i] : v[i + 8];
        float got  = __shfl_xor_sync(0xffffffffu, send, 4);
        float keep = (sub & 4) ? v[i + 8] : v[i];
        v[i] = keep + got;
    }
#pragma unroll
    for (int i = 0; i < 4; i++) {
        float send = (sub & 2) ? v[i] : v[i + 4];
        float got  = __shfl_xor_sync(0xffffffffu, send, 2);
        float keep = (sub & 2) ? v[i + 4] : v[i];
        v[i] = keep + got;
    }
#pragma unroll
    for (int i = 0; i < 2; i++) {
        float send = (sub & 1) ? v[i] : v[i + 2];
        float got  = __shfl_xor_sync(0xffffffffu, send, 1);
        float keep = (sub & 1) ? v[i + 2] : v[i];
        v[i] = keep + got;
    }
}

// ---------------- kernel 1: zero accumulators ----------------
__global__ void zero_kernel() {
    int i = blockIdx.x * blockDim.x + threadIdx.x;
    float4 z = make_float4(0.f, 0.f, 0.f, 0.f);
    if (i < NN * DN / 4) {
        reinterpret_cast<float4*>(g_user_msg)[i] = z;
        reinterpret_cast<float4*>(g_item_msg)[i] = z;
    }
    if (i < NN / 4) {
        reinterpret_cast<float4*>(g_norm_u)[i] = z;
        reinterpret_cast<float4*>(g_norm_i)[i] = z;
    }
}

// ---------------- kernel 2: hu = uh @ Wfwd^T, hi = ih @ Wrev^T ----------------
__global__ void proj_kernel(const float* __restrict__ user_h,
                            const float* __restrict__ item_h,
                            const float* __restrict__ w_fwd,
                            const float* __restrict__ w_rev,
                            const int* __restrict__ kptr) {
    int idx = blockIdx.x * blockDim.x + threadIdx.x;
    if (idx >= R * NN) return;
    int side = blockIdx.y;
    int r = idx / NN, n = idx % NN;
    int kk = *kptr;

    const float* h = (side ? item_h : user_h) + ((size_t)(kk * R + r) * NN + n) * DN;
    const float* W = (side ? w_rev : w_fwd) + r * DN * DN;
    float* out = (side ? g_hi : g_hu) + ((size_t)r * NN + n) * DN;

    float x[DN];
#pragma unroll
    for (int i = 0; i < 4; i++) {
        float4 t = reinterpret_cast<const float4*>(h)[i];
        x[4*i+0] = t.x; x[4*i+1] = t.y; x[4*i+2] = t.z; x[4*i+3] = t.w;
    }
#pragma unroll
    for (int o = 0; o < DN; o++) {
        float acc = 0.f;
#pragma unroll
        for (int d = 0; d < DN; d++) acc += x[d] * __ldg(&W[o * DN + d]);
        out[o] = acc;
    }
}

// ---------------- kernel 3: blend (4 edges/warp, 8 lanes/edge) ----------------
// Computes blended weight + norm accumulators + per-edge rfw/rfr projections.
__global__ void blend_kernel(const float* __restrict__ user_h,
                             const float* __restrict__ item_h,
                             const float* __restrict__ user_hsum,
                             const float* __restrict__ item_hsum,
                             const float* __restrict__ review_feat,
                             const float* __restrict__ prototypes,
                             const float* __restrict__ eta,
                             const float* __restrict__ rw_fwd,
                             const float* __restrict__ rw_rev,
                             const int* __restrict__ edge_src,
                             const int* __restrict__ edge_dst,
                             const int* __restrict__ kptr) {
    __shared__ float4 sproto[NF * DR / 4];   // 64
    __shared__ float4 sWf[DN * DR / 4];      // 256
    __shared__ float4 sWr[DN * DR / 4];      // 256
    int tid = threadIdx.x;
    int r = blockIdx.y;
    {
        const float4* p4  = reinterpret_cast<const float4*>(prototypes);
        const float4* wf4 = reinterpret_cast<const float4*>(rw_fwd + r * DN * DR);
        const float4* wr4 = reinterpret_cast<const float4*>(rw_rev + r * DN * DR);
        for (int i = tid; i < 576; i += 256) {
            if (i < 64)       sproto[i] = p4[i];
            else if (i < 320) sWf[i - 64] = wf4[i - 64];
            else              sWr[i - 320] = wr4[i - 320];
        }
    }
    __syncthreads();

    int warp = tid >> 5, lane = tid & 31, g = lane >> 3, sub = lane & 7;
    int e = (blockIdx.x * 8 + warp) * 4 + g;
    bool valid = e < E;
    int ec = valid ? e : E - 1;
    int kk = *kptr;
    int id = r * E + ec;
    int src = edge_src[id];
    int dst = edge_dst[id];

    // ---- stream rf row (256 floats), anchor partials ----
    const float4* rf4 = reinterpret_cast<const float4*>(review_feat + (size_t)id * (NF * DR));
    float4 q[8];
    float af[4] = {0.f, 0.f, 0.f, 0.f};
#pragma unroll
    for (int j = 0; j < 8; j++) {
        q[j] = rf4[sub + 8 * j];
        af[j >> 1] += dot4(q[j], sproto[sub + 8 * j]);
    }
#pragma unroll
    for (int o = 1; o < 8; o <<= 1) {
        af[0] += __shfl_xor_sync(0xffffffffu, af[0], o);
        af[1] += __shfl_xor_sync(0xffffffffu, af[1], o);
        af[2] += __shfl_xor_sync(0xffffffffu, af[2], o);
        af[3] += __shfl_xor_sync(0xffffffffu, af[3], o);
    }

    // ---- sim_all denominator (hsum, 64 floats each side) ----
    const float4* ra = reinterpret_cast<const float4*>(user_hsum + ((size_t)r * NN + src) * (NF * DN));
    const float4* ca = reinterpret_cast<const float4*>(item_hsum + ((size_t)r * NN + dst) * (NF * DN));
    float p = dot4(ra[2 * sub], ca[2 * sub]) + dot4(ra[2 * sub + 1], ca[2 * sub + 1]);
    p += __shfl_xor_sync(0xffffffffu, p, 1);         // full dot for f = sub/2
    float ex = __expf(2.f * p);
    ex += __shfl_xor_sync(0xffffffffu, ex, 2);
    ex += __shfl_xor_sync(0xffffffffu, ex, 4);
    float denom_sim = ex;                            // each f counted once

    // ---- cosine sim (lanes sub<4 of each group) ----
    float uu = 0.f, vv = 0.f, uv = 0.f;
    if (sub < 4) {
        float4 a = reinterpret_cast<const float4*>(user_h + ((size_t)(kk * R + r) * NN + src) * DN)[sub];
        float4 b = reinterpret_cast<const float4*>(item_h + ((size_t)(kk * R + r) * NN + dst) * DN)[sub];
        uu = dot4(a, a); vv = dot4(b, b); uv = dot4(a, b);
    }
    uu += __shfl_xor_sync(0xffffffffu, uu, 1); uu += __shfl_xor_sync(0xffffffffu, uu, 2);
    vv += __shfl_xor_sync(0xffffffffu, vv, 1); vv += __shfl_xor_sync(0xffffffffu, vv, 2);
    uv += __shfl_xor_sync(0xffffffffu, uv, 1); uv += __shfl_xor_sync(0xffffffffu, uv, 2);

    // ---- rf_k matvec against Wf, Wr (partials over this lane's 8 floats) ----
    float4 xa = q[0], xb = q[1];
#pragma unroll
    for (int j = 0; j < 8; j++) {
        if (j == 2 * kk)     xa = q[j];
        if (j == 2 * kk + 1) xb = q[j];
    }
    float vf[16], vr[16];
#pragma unroll
    for (int o = 0; o < 16; o++) {
        vf[o] = dot4(xa, sWf[o * 16 + sub]) + dot4(xb, sWf[o * 16 + 8 + sub]);
        vr[o] = dot4(xa, sWr[o * 16 + sub]) + dot4(xb, sWr[o * 16 + 8 + sub]);
    }
    rs8(vf, sub);
    rs8(vr, sub);
    if (valid) {
        reinterpret_cast<float2*>(g_rfw)[(size_t)id * 8 + sub] = make_float2(vf[0], vf[1]);
        reinterpret_cast<float2*>(g_rfr)[(size_t)id * 8 + sub] = make_float2(vr[0], vr[1]);
    }

    // ---- blended weight (lane sub==0 of each group) ----
    if (sub == 0 && valid) {
        float nu = fmaxf(sqrtf(uu), 1e-12f);
        float nv = fmaxf(sqrtf(vv), 1e-12f);
        float sim_k = 2.f * uv / (nu * nv);
        float exp_sim = __expf(sim_k) / denom_sim;

        float a0 = 2.f * af[0], a1 = 2.f * af[1], a2 = 2.f * af[2], a3 = 2.f * af[3];
        float denom_a = __expf(a0) + __expf(a1) + __expf(a2) + __expf(a3);
        float ak = (kk == 0) ? a0 : (kk == 1) ? a1 : (kk == 2) ? a2 : a3;
        float exp_anchor = __expf(ak) / denom_a;

        float gs = 1.f / (1.f + __expf(-eta[id]));
        float bl = gs * exp_anchor + (1.f - gs) * exp_sim;

        g_blended[id] = bl;
        atomicAdd(&g_norm_u[src], bl);
        atomicAdd(&g_norm_i[dst], bl);
    }
}

// ---------------- kernel 4: normalize + message scatter (thread per edge) ----------------
// item_msg[dst] += w*(hu[r,src]+rfw) ; user_msg[src] += w*(hi[r,dst]+rfr)
__global__ void scatter_kernel(const int* __restrict__ edge_src,
                               const int* __restrict__ edge_dst,
                               float* __restrict__ out_int_dist) {
    int r = blockIdx.y;
    int e = blockIdx.x * blockDim.x + threadIdx.x;
    if (e >= E) return;
    int id = r * E + e;

    int src = edge_src[id];
    int dst = edge_dst[id];
    float w = g_blended[id] * rsqrtf(g_norm_u[src] * g_norm_i[dst]);
    out_int_dist[id] = w;

    const float4* hu4 = reinterpret_cast<const float4*>(g_hu + ((size_t)r * NN + src) * DN);
    const float4* hi4 = reinterpret_cast<const float4*>(g_hi + ((size_t)r * NN + dst) * DN);
    const float4* fw4 = reinterpret_cast<const float4*>(g_rfw + (size_t)id * DN);
    const float4* fr4 = reinterpret_cast<const float4*>(g_rfr + (size_t)id * DN);
    float* im = g_item_msg + (size_t)dst * DN;
    float* um = g_user_msg + (size_t)src * DN;
#pragma unroll
    for (int i = 0; i < 4; i++) {
        float4 a = hu4[i], b = fw4[i];
        red_add_v4(im + 4 * i, make_float4(w*(a.x+b.x), w*(a.y+b.y), w*(a.z+b.z), w*(a.w+b.w)));
        float4 a2 = hi4[i], b2 = fr4[i];
        red_add_v4(um + 4 * i, make_float4(w*(a2.x+b2.x), w*(a2.y+b2.y), w*(a2.z+b2.z), w*(a2.w+b2.w)));
    }
}

// ---------------- kernel 5: leaky_relu + FC for users and items ----------------
__global__ void fc_kernel(const float* __restrict__ ufc_w, const float* __restrict__ ufc_b,
                          const float* __restrict__ ifc_w, const float* __restrict__ ifc_b,
                          float* __restrict__ out) {
    __shared__ float sW[2][DO * DN];
    __shared__ float sB[2][DO];
    int tid = threadIdx.x;   // 256
    for (int i = tid; i < DO * DN; i += 256) { sW[0][i] = ufc_w[i]; sW[1][i] = ifc_w[i]; }
    if (tid < DO) { sB[0][tid] = ufc_b[tid]; sB[1][tid] = ifc_b[tid]; }
    __syncthreads();

    int node = blockIdx.x * (256 / DO) + tid / DO;
    int o = tid % DO;
    if (node >= 2 * NN) return;
    int side = node >= NN;
    int n = side ? node - NN : node;
    const float* msg = (side ? g_item_msg : g_user_msg) + (size_t)n * DN;

    float acc = sB[side][o];
#pragma unroll
    for (int d = 0; d < DN; d++) {
        float m = msg[d];
        m = (m >= 0.f) ? m : 0.1f * m;
        acc += m * sW[side][o * DN + d];
    }
    out[(size_t)node * DO + o] = acc;
}

// ---------------- launch ----------------
extern "C" void kernel_launch(void* const* d_in, const int* in_sizes, int n_in,
                              void* d_out, int out_size) {
    const float* user_h      = (const float*)d_in[0];
    const float* item_h      = (const float*)d_in[1];
    const float* user_hsum   = (const float*)d_in[2];
    const float* item_hsum   = (const float*)d_in[3];
    const float* review_feat = (const float*)d_in[4];
    const float* prototypes  = (const float*)d_in[5];
    const float* eta         = (const float*)d_in[6];
    const float* node_w_fwd  = (const float*)d_in[7];
    const float* review_w_fwd= (const float*)d_in[8];
    const float* node_w_rev  = (const float*)d_in[9];
    const float* review_w_rev= (const float*)d_in[10];
    const float* ufc_w       = (const float*)d_in[11];
    const float* ufc_b       = (const float*)d_in[12];
    const float* ifc_w       = (const float*)d_in[13];
    const float* ifc_b       = (const float*)d_in[14];
    const int*   edge_src    = (const int*)d_in[15];
    const int*   edge_dst    = (const int*)d_in[16];
    const int*   kptr        = (const int*)d_in[17];

    float* out = (float*)d_out;
    float* out_int = out + (size_t)2 * NN * DO;   // int_dist after ufeat+ifeat

    zero_kernel<<<(NN * DN / 4 + 255) / 256, 256>>>();

    dim3 gp((R * NN + 255) / 256, 2);
    proj_kernel<<<gp, 256>>>(user_h, item_h, node_w_fwd, node_w_rev, kptr);

    dim3 gb((E + 31) / 32, R);   // 32 edges per 256-thread block
    blend_kernel<<<gb, 256>>>(user_h, item_h, user_hsum, item_hsum,
                              review_feat, prototypes, eta,
                              review_w_fwd, review_w_rev,
                              edge_src, edge_dst, kptr);

    dim3 gs((E + 255) / 256, R);
    scatter_kernel<<<gs, 256>>>(edge_src, edge_dst, out_int);

    fc_kernel<<<(2 * NN * DO) / 256, 256>>>(ufc_w, ufc_b, ifc_w, ifc_b, out);
}

// round 7
// speedup vs baseline: 1.3624x; 1.2409x over previous
#include <cuda_runtime.h>
#include <cstdint>

#define R  5
#define E  50000
#define NN 20000      // NU == NI
#define NF 4
#define DN 16
#define DR 64
#define DO 64
// TAU = 0.5 -> 1/TAU = 2.0f

// ---------------- scratch (device globals; no allocation) ----------------
__device__ __align__(16) float g_blended[R * E];
__device__ __align__(16) float g_norm_u[NN];
__device__ __align__(16) float g_norm_i[NN];
__device__ __align__(16) float g_hu[R * NN * DN];
__device__ __align__(16) float g_hi[R * NN * DN];
__device__ __align__(16) float g_user_msg[NN * DN];
__device__ __align__(16) float g_item_msg[NN * DN];
__device__ __align__(16) float g_mf[(size_t)R * E * DN];   // m_fwd = hu[src] + rf_k@Wf^T
__device__ __align__(16) float g_mr[(size_t)R * E * DN];   // m_rev = hi[dst] + rf_k@Wr^T

__device__ __forceinline__ float dot4(float4 a, float4 b) {
    return a.x * b.x + a.y * b.y + a.z * b.z + a.w * b.w;
}

// vector global reduction (sm_90+): 4 floats in one RED
__device__ __forceinline__ void red_add_v4(float* p, float4 m) {
    asm volatile("red.global.add.v4.f32 [%0], {%1, %2, %3, %4};"
                 :: "l"(p), "f"(m.x), "f"(m.y), "f"(m.z), "f"(m.w)
                 : "memory");
}

// ---------------- kernel 1: zero accumulators ----------------
__global__ void zero_kernel() {
    int i = blockIdx.x * blockDim.x + threadIdx.x;
    float4 z = make_float4(0.f, 0.f, 0.f, 0.f);
    if (i < NN * DN / 4) {
        reinterpret_cast<float4*>(g_user_msg)[i] = z;
        reinterpret_cast<float4*>(g_item_msg)[i] = z;
    }
    if (i < NN / 4) {
        reinterpret_cast<float4*>(g_norm_u)[i] = z;
        reinterpret_cast<float4*>(g_norm_i)[i] = z;
    }
}

// ---------------- kernel 2a/2b: hu = uh @ Wfwd^T  /  hi = ih @ Wrev^T ----------------
__global__ void proj_kernel(const float* __restrict__ h_in,
                            const float* __restrict__ w_in,
                            float* __restrict__ h_out,
                            const int* __restrict__ kptr) {
    int idx = blockIdx.x * blockDim.x + threadIdx.x;
    if (idx >= R * NN) return;
    int r = idx / NN, n = idx % NN;
    int kk = *kptr;

    const float* h = h_in + ((size_t)(kk * R + r) * NN + n) * DN;
    const float* W = w_in + r * DN * DN;
    float* out = h_out + ((size_t)r * NN + n) * DN;

    float x[DN];
#pragma unroll
    for (int i = 0; i < 4; i++) {
        float4 t = reinterpret_cast<const float4*>(h)[i];
        x[4*i+0] = t.x; x[4*i+1] = t.y; x[4*i+2] = t.z; x[4*i+3] = t.w;
    }
#pragma unroll
    for (int o = 0; o < DN; o++) {
        float acc = 0.f;
#pragma unroll
        for (int d = 0; d < DN; d++) acc += x[d] * __ldg(&W[o * DN + d]);
        out[o] = acc;
    }
}

// ---------------- kernel 3: blend (4 edges/warp, 8 lanes/edge) ----------------
// Per edge: blended weight + norm atomics + m_fwd/m_rev stores.
// Matvec: rf_k staged in SMEM; each lane computes 2 full outputs (no reduce-scatter).
__global__ __launch_bounds__(256)
void blend_kernel(const float* __restrict__ user_h,
                  const float* __restrict__ item_h,
                  const float* __restrict__ user_hsum,
                  const float* __restrict__ item_hsum,
                  const float* __restrict__ review_feat,
                  const float* __restrict__ prototypes,
                  const float* __restrict__ eta,
                  const float* __restrict__ rw_fwd,
                  const float* __restrict__ rw_rev,
                  const int* __restrict__ edge_src,
                  const int* __restrict__ edge_dst,
                  const int* __restrict__ kptr) {
    __shared__ float4 sproto[NF * DR / 4];   // 64 float4
    __shared__ float4 sWf[DN * 17];          // row o at o*17 (16 used + 1 pad) -> 2-phase LDS
    __shared__ float4 sWr[DN * 17];
    __shared__ float4 sRF[8][4][17];         // [warp][group][16 float4 + pad] -> conflict-free

    int tid = threadIdx.x;
    int r = blockIdx.y;
    {
        const float4* p4  = reinterpret_cast<const float4*>(prototypes);
        const float4* wf4 = reinterpret_cast<const float4*>(rw_fwd + r * DN * DR);
        const float4* wr4 = reinterpret_cast<const float4*>(rw_rev + r * DN * DR);
        for (int i = tid; i < 576; i += 256) {
            if (i < 64) {
                sproto[i] = p4[i];
            } else if (i < 320) {
                int idx = i - 64; int o = idx >> 4, d = idx & 15;
                sWf[o * 17 + d] = wf4[idx];
            } else {
                int idx = i - 320; int o = idx >> 4, d = idx & 15;
                sWr[o * 17 + d] = wr4[idx];
            }
        }
    }
    __syncthreads();

    int warp = tid >> 5, lane = tid & 31, g = lane >> 3, sub = lane & 7;
    int e = (blockIdx.x * 8 + warp) * 4 + g;
    bool valid = e < E;
    int ec = valid ? e : E - 1;
    int kk = *kptr;
    int id = r * E + ec;
    int src = edge_src[id];
    int dst = edge_dst[id];

    // early gathers: projected node vectors (this lane's 2 output dims)
    float2 hu2 = *reinterpret_cast<const float2*>(g_hu + ((size_t)r * NN + src) * DN + 2 * sub);
    float2 hi2 = *reinterpret_cast<const float2*>(g_hi + ((size_t)r * NN + dst) * DN + 2 * sub);

    // ---- sim_all denominator (hsum, 64 floats each side) ----
    const float4* ra = reinterpret_cast<const float4*>(user_hsum + ((size_t)r * NN + src) * (NF * DN));
    const float4* ca = reinterpret_cast<const float4*>(item_hsum + ((size_t)r * NN + dst) * (NF * DN));
    float p = dot4(ra[2 * sub], ca[2 * sub]) + dot4(ra[2 * sub + 1], ca[2 * sub + 1]);
    p += __shfl_xor_sync(0xffffffffu, p, 1);        // full dot for factor f = sub/2
    float ex = __expf(2.f * p);
    ex += __shfl_xor_sync(0xffffffffu, ex, 2);
    ex += __shfl_xor_sync(0xffffffffu, ex, 4);
    float denom_sim = ex;                           // each f counted once

    // ---- cosine sim (lanes sub<4 of each group) ----
    float uu = 0.f, vv = 0.f, uv = 0.f;
    if (sub < 4) {
        float4 a = reinterpret_cast<const float4*>(user_h + ((size_t)(kk * R + r) * NN + src) * DN)[sub];
        float4 b = reinterpret_cast<const float4*>(item_h + ((size_t)(kk * R + r) * NN + dst) * DN)[sub];
        uu = dot4(a, a); vv = dot4(b, b); uv = dot4(a, b);
    }
    uu += __shfl_xor_sync(0xffffffffu, uu, 1); uu += __shfl_xor_sync(0xffffffffu, uu, 2);
    vv += __shfl_xor_sync(0xffffffffu, vv, 1); vv += __shfl_xor_sync(0xffffffffu, vv, 2);
    uv += __shfl_xor_sync(0xffffffffu, uv, 1); uv += __shfl_xor_sync(0xffffffffu, uv, 2);

    // ---- stream rf row (256 floats): anchor partials + stage k-slice to SMEM ----
    const float4* rf4 = reinterpret_cast<const float4*>(review_feat + (size_t)id * (NF * DR));
    float af[4] = {0.f, 0.f, 0.f, 0.f};
    int j0 = 2 * kk, j1 = 2 * kk + 1;
#pragma unroll
    for (int j = 0; j < 8; j++) {
        float4 q = rf4[sub + 8 * j];
        af[j >> 1] += dot4(q, sproto[sub + 8 * j]);
        if (j == j0) sRF[warp][g][sub] = q;
        if (j == j1) sRF[warp][g][8 + sub] = q;
    }
    __syncwarp();
#pragma unroll
    for (int o = 1; o < 8; o <<= 1) {
        af[0] += __shfl_xor_sync(0xffffffffu, af[0], o);
        af[1] += __shfl_xor_sync(0xffffffffu, af[1], o);
        af[2] += __shfl_xor_sync(0xffffffffu, af[2], o);
        af[3] += __shfl_xor_sync(0xffffffffu, af[3], o);
    }

    // ---- matvec: lane sub computes outputs {2sub, 2sub+1} for both matrices ----
    float f0 = 0.f, f1 = 0.f, r0 = 0.f, r1 = 0.f;
    const float4* xrow = &sRF[warp][g][0];
    int o0 = 2 * sub * 17, o1 = (2 * sub + 1) * 17;
#pragma unroll
    for (int d4 = 0; d4 < 16; d4++) {
        float4 x = xrow[d4];
        f0 += dot4(x, sWf[o0 + d4]);
        f1 += dot4(x, sWf[o1 + d4]);
        r0 += dot4(x, sWr[o0 + d4]);
        r1 += dot4(x, sWr[o1 + d4]);
    }
    if (valid) {
        *reinterpret_cast<float2*>(g_mf + (size_t)id * DN + 2 * sub) = make_float2(hu2.x + f0, hu2.y + f1);
        *reinterpret_cast<float2*>(g_mr + (size_t)id * DN + 2 * sub) = make_float2(hi2.x + r0, hi2.y + r1);
    }

    // ---- blended weight (lane sub==0 of each group) ----
    if (sub == 0 && valid) {
        float nu = fmaxf(sqrtf(uu), 1e-12f);
        float nv = fmaxf(sqrtf(vv), 1e-12f);
        float sim_k = 2.f * uv / (nu * nv);
        float exp_sim = __expf(sim_k) / denom_sim;

        float a0 = 2.f * af[0], a1 = 2.f * af[1], a2 = 2.f * af[2], a3 = 2.f * af[3];
        float denom_a = __expf(a0) + __expf(a1) + __expf(a2) + __expf(a3);
        float ak = (kk == 0) ? a0 : (kk == 1) ? a1 : (kk == 2) ? a2 : a3;
        float exp_anchor = __expf(ak) / denom_a;

        float gs = 1.f / (1.f + __expf(-eta[id]));
        float bl = gs * exp_anchor + (1.f - gs) * exp_sim;

        g_blended[id] = bl;
        atomicAdd(&g_norm_u[src], bl);
        atomicAdd(&g_norm_i[dst], bl);
    }
}

// ---------------- kernel 4: normalize + message scatter (thread per edge) ----------------
// All loads coalesced except scalar norm gathers (L2-resident).
__global__ void scatter_kernel(const int* __restrict__ edge_src,
                               const int* __restrict__ edge_dst,
                               float* __restrict__ out_int_dist) {
    int r = blockIdx.y;
    int e = blockIdx.x * blockDim.x + threadIdx.x;
    if (e >= E) return;
    int id = r * E + e;

    int src = edge_src[id];
    int dst = edge_dst[id];
    float w = g_blended[id] * rsqrtf(g_norm_u[src] * g_norm_i[dst]);
    out_int_dist[id] = w;

    const float4* mf4 = reinterpret_cast<const float4*>(g_mf + (size_t)id * DN);
    const float4* mr4 = reinterpret_cast<const float4*>(g_mr + (size_t)id * DN);
    float* im = g_item_msg + (size_t)dst * DN;
    float* um = g_user_msg + (size_t)src * DN;
#pragma unroll
    for (int i = 0; i < 4; i++) {
        float4 a = mf4[i];
        red_add_v4(im + 4 * i, make_float4(w * a.x, w * a.y, w * a.z, w * a.w));
        float4 b = mr4[i];
        red_add_v4(um + 4 * i, make_float4(w * b.x, w * b.y, w * b.z, w * b.w));
    }
}

// ---------------- kernel 5: leaky_relu + FC for users and items ----------------
__global__ void fc_kernel(const float* __restrict__ ufc_w, const float* __restrict__ ufc_b,
                          const float* __restrict__ ifc_w, const float* __restrict__ ifc_b,
                          float* __restrict__ out) {
    __shared__ float sW[2][DO * DN];
    __shared__ float sB[2][DO];
    int tid = threadIdx.x;   // 256
    for (int i = tid; i < DO * DN; i += 256) { sW[0][i] = ufc_w[i]; sW[1][i] = ifc_w[i]; }
    if (tid < DO) { sB[0][tid] = ufc_b[tid]; sB[1][tid] = ifc_b[tid]; }
    __syncthreads();

    int node = blockIdx.x * (256 / DO) + tid / DO;
    int o = tid % DO;
    if (node >= 2 * NN) return;
    int side = node >= NN;
    int n = side ? node - NN : node;
    const float* msg = (side ? g_item_msg : g_user_msg) + (size_t)n * DN;

    float acc = sB[side][o];
#pragma unroll
    for (int d = 0; d < DN; d++) {
        float m = msg[d];
        m = (m >= 0.f) ? m : 0.1f * m;
        acc += m * sW[side][o * DN + d];
    }
    out[(size_t)node * DO + o] = acc;
}

// ---------------- launch ----------------
extern "C" void kernel_launch(void* const* d_in, const int* in_sizes, int n_in,
                              void* d_out, int out_size) {
    const float* user_h      = (const float*)d_in[0];
    const float* item_h      = (const float*)d_in[1];
    const float* user_hsum   = (const float*)d_in[2];
    const float* item_hsum   = (const float*)d_in[3];
    const float* review_feat = (const float*)d_in[4];
    const float* prototypes  = (const float*)d_in[5];
    const float* eta         = (const float*)d_in[6];
    const float* node_w_fwd  = (const float*)d_in[7];
    const float* review_w_fwd= (const float*)d_in[8];
    const float* node_w_rev  = (const float*)d_in[9];
    const float* review_w_rev= (const float*)d_in[10];
    const float* ufc_w       = (const float*)d_in[11];
    const float* ufc_b       = (const float*)d_in[12];
    const float* ifc_w       = (const float*)d_in[13];
    const float* ifc_b       = (const float*)d_in[14];
    const int*   edge_src    = (const int*)d_in[15];
    const int*   edge_dst    = (const int*)d_in[16];
    const int*   kptr        = (const int*)d_in[17];

    float* out = (float*)d_out;
    float* out_int = out + (size_t)2 * NN * DO;   // int_dist after ufeat+ifeat

    // launch 1
    zero_kernel<<<(NN * DN / 4 + 255) / 256, 256>>>();

    // launches 2, 3 (split so blend is the 4th = profiled launch)
    int gp = (R * NN + 255) / 256;
    float* g_hu_p; cudaGetSymbolAddress((void**)&g_hu_p, g_hu);
    float* g_hi_p; cudaGetSymbolAddress((void**)&g_hi_p, g_hi);
    proj_kernel<<<gp, 256>>>(user_h, node_w_fwd, g_hu_p, kptr);
    proj_kernel<<<gp, 256>>>(item_h, node_w_rev, g_hi_p, kptr);

    // launch 4: blend (profiled slot)
    dim3 gb((E + 31) / 32, R);   // 32 edges per 256-thread block
    blend_kernel<<<gb, 256>>>(user_h, item_h, user_hsum, item_hsum,
                              review_feat, prototypes, eta,
                              review_w_fwd, review_w_rev,
                              edge_src, edge_dst, kptr);

    // launch 5
    dim3 gs((E + 255) / 256, R);
    scatter_kernel<<<gs, 256>>>(edge_src, edge_dst, out_int);

    // launch 6
    fc_kernel<<<(2 * NN * DO) / 256, 256>>>(ufc_w, ufc_b, ifc_w, ifc_b, out);
}

// round 8
// speedup vs baseline: 2.0721x; 1.5209x over previous
#include <cuda_runtime.h>
#include <cstdint>

#define R  5
#define E  50000
#define NN 20000      // NU == NI
#define NF 4
#define DN 16
#define DR 64
#define DO 64
#define TILE_E 128
// TAU = 0.5 -> 1/TAU = 2.0f

// ---------------- scratch (device globals; no allocation) ----------------
__device__ __align__(16) float g_blended[R * E];
__device__ __align__(16) float g_norm_u[NN];
__device__ __align__(16) float g_norm_i[NN];
__device__ __align__(16) float g_hu[R * NN * DN];
__device__ __align__(16) float g_hi[R * NN * DN];
__device__ __align__(16) float g_user_msg[NN * DN];
__device__ __align__(16) float g_item_msg[NN * DN];

__device__ __forceinline__ float dot4(float4 a, float4 b) {
    return a.x * b.x + a.y * b.y + a.z * b.z + a.w * b.w;
}

// vector global reduction (sm_90+): 4 floats in one RED
__device__ __forceinline__ void red_add_v4(float* p, float4 m) {
    asm volatile("red.global.add.v4.f32 [%0], {%1, %2, %3, %4};"
                 :: "l"(p), "f"(m.x), "f"(m.y), "f"(m.z), "f"(m.w)
                 : "memory");
}

// ---------------- kernel 1: zero accumulators ----------------
__global__ void zero_kernel() {
    int i = blockIdx.x * blockDim.x + threadIdx.x;
    float4 z = make_float4(0.f, 0.f, 0.f, 0.f);
    if (i < NN * DN / 4) {
        reinterpret_cast<float4*>(g_user_msg)[i] = z;
        reinterpret_cast<float4*>(g_item_msg)[i] = z;
    }
    if (i < NN / 4) {
        reinterpret_cast<float4*>(g_norm_u)[i] = z;
        reinterpret_cast<float4*>(g_norm_i)[i] = z;
    }
}

// ---------------- kernel 2a/2b: hu = uh @ Wfwd^T  /  hi = ih @ Wrev^T ----------------
__global__ void proj_kernel(const float* __restrict__ h_in,
                            const float* __restrict__ w_in,
                            float* __restrict__ h_out,
                            const int* __restrict__ kptr) {
    int idx = blockIdx.x * blockDim.x + threadIdx.x;
    if (idx >= R * NN) return;
    int r = idx / NN, n = idx % NN;
    int kk = *kptr;

    const float* h = h_in + ((size_t)(kk * R + r) * NN + n) * DN;
    const float* W = w_in + r * DN * DN;
    float* out = h_out + ((size_t)r * NN + n) * DN;

    float x[DN];
#pragma unroll
    for (int i = 0; i < 4; i++) {
        float4 t = reinterpret_cast<const float4*>(h)[i];
        x[4*i+0] = t.x; x[4*i+1] = t.y; x[4*i+2] = t.z; x[4*i+3] = t.w;
    }
#pragma unroll
    for (int o = 0; o < DN; o++) {
        float acc = 0.f;
#pragma unroll
        for (int d = 0; d < DN; d++) acc += x[d] * __ldg(&W[o * DN + d]);
        out[o] = acc;
    }
}

// ---------------- kernel 3: blend-lite (4 edges/warp, 8 lanes/edge) ----------------
// Pure softmax/blend pass: streams review_feat once, no matvec, no staging.
__global__ __launch_bounds__(256)
void blend_kernel(const float* __restrict__ user_h,
                  const float* __restrict__ item_h,
                  const float* __restrict__ user_hsum,
                  const float* __restrict__ item_hsum,
                  const float* __restrict__ review_feat,
                  const float* __restrict__ prototypes,
                  const float* __restrict__ eta,
                  const int* __restrict__ edge_src,
                  const int* __restrict__ edge_dst,
                  const int* __restrict__ kptr) {
    __shared__ float4 sproto[NF * DR / 4];   // 64 float4
    int tid = threadIdx.x;
    int r = blockIdx.y;
    if (tid < 64) sproto[tid] = reinterpret_cast<const float4*>(prototypes)[tid];
    __syncthreads();

    int warp = tid >> 5, lane = tid & 31, g = lane >> 3, sub = lane & 7;
    int e = (blockIdx.x * 8 + warp) * 4 + g;
    bool valid = e < E;
    int ec = valid ? e : E - 1;
    int kk = *kptr;
    int id = r * E + ec;
    int src = edge_src[id];
    int dst = edge_dst[id];

    // ---- sim_all denominator (hsum, 64 floats each side) ----
    const float4* ra = reinterpret_cast<const float4*>(user_hsum + ((size_t)r * NN + src) * (NF * DN));
    const float4* ca = reinterpret_cast<const float4*>(item_hsum + ((size_t)r * NN + dst) * (NF * DN));
    float p = dot4(ra[2 * sub], ca[2 * sub]) + dot4(ra[2 * sub + 1], ca[2 * sub + 1]);
    p += __shfl_xor_sync(0xffffffffu, p, 1);        // full dot for factor f = sub/2
    float ex = __expf(2.f * p);
    ex += __shfl_xor_sync(0xffffffffu, ex, 2);
    ex += __shfl_xor_sync(0xffffffffu, ex, 4);
    float denom_sim = ex;                           // each f counted once

    // ---- cosine sim (lanes sub<4 of each group) ----
    float uu = 0.f, vv = 0.f, uv = 0.f;
    if (sub < 4) {
        float4 a = reinterpret_cast<const float4*>(user_h + ((size_t)(kk * R + r) * NN + src) * DN)[sub];
        float4 b = reinterpret_cast<const float4*>(item_h + ((size_t)(kk * R + r) * NN + dst) * DN)[sub];
        uu = dot4(a, a); vv = dot4(b, b); uv = dot4(a, b);
    }
    uu += __shfl_xor_sync(0xffffffffu, uu, 1); uu += __shfl_xor_sync(0xffffffffu, uu, 2);
    vv += __shfl_xor_sync(0xffffffffu, vv, 1); vv += __shfl_xor_sync(0xffffffffu, vv, 2);
    uv += __shfl_xor_sync(0xffffffffu, uv, 1); uv += __shfl_xor_sync(0xffffffffu, uv, 2);

    // ---- anchors: stream rf row (256 floats), 8-lane-coalesced ----
    const float4* rf4 = reinterpret_cast<const float4*>(review_feat + (size_t)id * (NF * DR));
    float af[4] = {0.f, 0.f, 0.f, 0.f};
#pragma unroll
    for (int j = 0; j < 8; j++) {
        float4 q = rf4[sub + 8 * j];
        af[j >> 1] += dot4(q, sproto[sub + 8 * j]);
    }
#pragma unroll
    for (int o = 1; o < 8; o <<= 1) {
        af[0] += __shfl_xor_sync(0xffffffffu, af[0], o);
        af[1] += __shfl_xor_sync(0xffffffffu, af[1], o);
        af[2] += __shfl_xor_sync(0xffffffffu, af[2], o);
        af[3] += __shfl_xor_sync(0xffffffffu, af[3], o);
    }

    // ---- blended weight (lane sub==0 of each group) ----
    if (sub == 0 && valid) {
        float nu = fmaxf(sqrtf(uu), 1e-12f);
        float nv = fmaxf(sqrtf(vv), 1e-12f);
        float sim_k = 2.f * uv / (nu * nv);
        float exp_sim = __expf(sim_k) / denom_sim;

        float a0 = 2.f * af[0], a1 = 2.f * af[1], a2 = 2.f * af[2], a3 = 2.f * af[3];
        float denom_a = __expf(a0) + __expf(a1) + __expf(a2) + __expf(a3);
        float ak = (kk == 0) ? a0 : (kk == 1) ? a1 : (kk == 2) ? a2 : a3;
        float exp_anchor = __expf(ak) / denom_a;

        float gs = 1.f / (1.f + __expf(-eta[id]));
        float bl = gs * exp_anchor + (1.f - gs) * exp_sim;

        g_blended[id] = bl;
        atomicAdd(&g_norm_u[src], bl);
        atomicAdd(&g_norm_i[dst], bl);
    }
}

// ---------------- kernel 4: tiled GEMM + fused normalize/gather/scatter ----------------
// Per block: 128 edges of one r. Y[128x32] = X[128x64] @ [Wf;Wr]^T, then
// m halves + hu/hi add, scale by w, RED into msg arrays. Also writes int_dist.
__global__ __launch_bounds__(128)
void gemm_scatter_kernel(const float* __restrict__ review_feat,
                         const float* __restrict__ rw_fwd,
                         const float* __restrict__ rw_rev,
                         const int* __restrict__ edge_src,
                         const int* __restrict__ edge_dst,
                         const int* __restrict__ kptr,
                         float* __restrict__ out_int_dist) {
    __shared__ float4 sW[32 * 16];     // rows 0-15 Wf, 16-31 Wr
    __shared__ float4 sX[16 * 129];    // transposed X: [d4][edge], pitch 129
    __shared__ float  sw_s[TILE_E];
    __shared__ int    ssrc[TILE_E];
    __shared__ int    sdst[TILE_E];

    int r = blockIdx.y;
    int tid = threadIdx.x;
    int e0 = blockIdx.x * TILE_E;
    int kk = *kptr;

    // stage W (stacked)
    {
        const float4* wf4 = reinterpret_cast<const float4*>(rw_fwd + r * DN * DR);
        const float4* wr4 = reinterpret_cast<const float4*>(rw_rev + r * DN * DR);
        for (int i = tid; i < 512; i += 128)
            sW[i] = (i < 256) ? wf4[i] : wr4[i - 256];
    }
    // stage X transposed (coalesced gmem, conflict-free STS)
    {
        int d4 = tid & 15, erow = tid >> 4;   // 8 edges per pass
#pragma unroll
        for (int pss = 0; pss < 16; pss++) {
            int e = erow + 8 * pss;
            int ge = e0 + e;
            float4 v = make_float4(0.f, 0.f, 0.f, 0.f);
            if (ge < E)
                v = reinterpret_cast<const float4*>(review_feat)[
                        ((size_t)(r * E + ge) * NF + kk) * (DR / 4) + d4];
            sX[d4 * 129 + e] = v;
        }
    }
    // per-edge normalized weight + int_dist
    {
        int ge = e0 + tid;
        float w = 0.f; int s = 0, d = 0;
        if (ge < E) {
            int id = r * E + ge;
            s = edge_src[id]; d = edge_dst[id];
            w = g_blended[id] * rsqrtf(g_norm_u[s] * g_norm_i[d]);
            out_int_dist[id] = w;
        }
        sw_s[tid] = w; ssrc[tid] = s; sdst[tid] = d;
    }
    __syncthreads();

    int eq = tid & 31, oo = tid >> 5;   // thread: 4 edges (eq+32j) x 8 outputs (8oo..)
    float acc[4][8];
#pragma unroll
    for (int j = 0; j < 4; j++)
#pragma unroll
        for (int o = 0; o < 8; o++) acc[j][o] = 0.f;

    const float4* wbase = sW + (8 * oo) * 16;
#pragma unroll
    for (int d4 = 0; d4 < 16; d4++) {
        float4 w0 = wbase[0 * 16 + d4], w1 = wbase[1 * 16 + d4];
        float4 w2 = wbase[2 * 16 + d4], w3 = wbase[3 * 16 + d4];
        float4 w4 = wbase[4 * 16 + d4], w5 = wbase[5 * 16 + d4];
        float4 w6 = wbase[6 * 16 + d4], w7 = wbase[7 * 16 + d4];
#pragma unroll
        for (int j = 0; j < 4; j++) {
            float4 x = sX[d4 * 129 + eq + 32 * j];
            acc[j][0] += dot4(x, w0); acc[j][1] += dot4(x, w1);
            acc[j][2] += dot4(x, w2); acc[j][3] += dot4(x, w3);
            acc[j][4] += dot4(x, w4); acc[j][5] += dot4(x, w5);
            acc[j][6] += dot4(x, w6); acc[j][7] += dot4(x, w7);
        }
    }

    bool fwd = oo < 2;      // outputs 0-15 = m_fwd, 16-31 = m_rev
    int half = oo & 1;      // which 8-float half of the 16-dim message
#pragma unroll
    for (int j = 0; j < 4; j++) {
        int et = eq + 32 * j;
        int ge = e0 + et;
        if (ge >= E) continue;
        float wv = sw_s[et];
        int s = ssrc[et], d = sdst[et];
        const float4* h4 = reinterpret_cast<const float4*>(
            fwd ? g_hu + ((size_t)r * NN + s) * DN
                : g_hi + ((size_t)r * NN + d) * DN) + 2 * half;
        float* tgt = (fwd ? g_item_msg + (size_t)d * DN
                          : g_user_msg + (size_t)s * DN) + 8 * half;
        float4 h0 = h4[0], h1 = h4[1];
        red_add_v4(tgt, make_float4((acc[j][0] + h0.x) * wv, (acc[j][1] + h0.y) * wv,
                                    (acc[j][2] + h0.z) * wv, (acc[j][3] + h0.w) * wv));
        red_add_v4(tgt + 4, make_float4((acc[j][4] + h1.x) * wv, (acc[j][5] + h1.y) * wv,
                                        (acc[j][6] + h1.z) * wv, (acc[j][7] + h1.w) * wv));
    }
}

// ---------------- kernel 5: leaky_relu + FC for users and items ----------------
__global__ void fc_kernel(const float* __restrict__ ufc_w, const float* __restrict__ ufc_b,
                          const float* __restrict__ ifc_w, const float* __restrict__ ifc_b,
                          float* __restrict__ out) {
    __shared__ float sW[2][DO * DN];
    __shared__ float sB[2][DO];
    int tid = threadIdx.x;   // 256
    for (int i = tid; i < DO * DN; i += 256) { sW[0][i] = ufc_w[i]; sW[1][i] = ifc_w[i]; }
    if (tid < DO) { sB[0][tid] = ufc_b[tid]; sB[1][tid] = ifc_b[tid]; }
    __syncthreads();

    int node = blockIdx.x * (256 / DO) + tid / DO;
    int o = tid % DO;
    if (node >= 2 * NN) return;
    int side = node >= NN;
    int n = side ? node - NN : node;
    const float* msg = (side ? g_item_msg : g_user_msg) + (size_t)n * DN;

    float acc = sB[side][o];
#pragma unroll
    for (int d = 0; d < DN; d++) {
        float m = msg[d];
        m = (m >= 0.f) ? m : 0.1f * m;
        acc += m * sW[side][o * DN + d];
    }
    out[(size_t)node * DO + o] = acc;
}

// ---------------- launch ----------------
extern "C" void kernel_launch(void* const* d_in, const int* in_sizes, int n_in,
                              void* d_out, int out_size) {
    const float* user_h      = (const float*)d_in[0];
    const float* item_h      = (const float*)d_in[1];
    const float* user_hsum   = (const float*)d_in[2];
    const float* item_hsum   = (const float*)d_in[3];
    const float* review_feat = (const float*)d_in[4];
    const float* prototypes  = (const float*)d_in[5];
    const float* eta         = (const float*)d_in[6];
    const float* node_w_fwd  = (const float*)d_in[7];
    const float* review_w_fwd= (const float*)d_in[8];
    const float* node_w_rev  = (const float*)d_in[9];
    const float* review_w_rev= (const float*)d_in[10];
    const float* ufc_w       = (const float*)d_in[11];
    const float* ufc_b       = (const float*)d_in[12];
    const float* ifc_w       = (const float*)d_in[13];
    const float* ifc_b       = (const float*)d_in[14];
    const int*   edge_src    = (const int*)d_in[15];
    const int*   edge_dst    = (const int*)d_in[16];
    const int*   kptr        = (const int*)d_in[17];

    float* out = (float*)d_out;
    float* out_int = out + (size_t)2 * NN * DO;   // int_dist after ufeat+ifeat

    // launch 1
    zero_kernel<<<(NN * DN / 4 + 255) / 256, 256>>>();

    // launches 2, 3
    int gp = (R * NN + 255) / 256;
    float* g_hu_p; cudaGetSymbolAddress((void**)&g_hu_p, g_hu);
    float* g_hi_p; cudaGetSymbolAddress((void**)&g_hi_p, g_hi);
    proj_kernel<<<gp, 256>>>(user_h, node_w_fwd, g_hu_p, kptr);
    proj_kernel<<<gp, 256>>>(item_h, node_w_rev, g_hi_p, kptr);

    // launch 4: blend-lite (profiled slot)
    dim3 gb((E + 31) / 32, R);   // 32 edges per 256-thread block
    blend_kernel<<<gb, 256>>>(user_h, item_h, user_hsum, item_hsum,
                              review_feat, prototypes, eta,
                              edge_src, edge_dst, kptr);

    // launch 5: fused GEMM + scatter
    dim3 gg((E + TILE_E - 1) / TILE_E, R);
    gemm_scatter_kernel<<<gg, 128>>>(review_feat, review_w_fwd, review_w_rev,
                                     edge_src, edge_dst, kptr, out_int);

    // launch 6
    fc_kernel<<<(2 * NN * DO) / 256, 256>>>(ufc_w, ufc_b, ifc_w, ifc_b, out);
}

// round 10
// speedup vs baseline: 2.0911x; 1.0092x over previous
#include <cuda_runtime.h>
#include <cstdint>

#define R  5
#define E  50000
#define NN 20000      // NU == NI
#define NF 4
#define DN 16
#define DR 64
#define DO 64
#define TILE_E 128
// TAU = 0.5 -> 1/TAU = 2.0f

// ---------------- scratch (device globals; no allocation) ----------------
__device__ __align__(16) float g_blended[R * E];
__device__ __align__(16) float g_norm_u[NN];
__device__ __align__(16) float g_norm_i[NN];
__device__ __align__(16) float g_hu[R * NN * DN];
__device__ __align__(16) float g_hi[R * NN * DN];
__device__ __align__(16) float g_user_msg[NN * DN];
__device__ __align__(16) float g_item_msg[NN * DN];

__device__ __forceinline__ float dot4(float4 a, float4 b) {
    return a.x * b.x + a.y * b.y + a.z * b.z + a.w * b.w;
}

// vector global reduction (sm_90+): 4 floats in one RED
__device__ __forceinline__ void red_add_v4(float* p, float4 m) {
    asm volatile("red.global.add.v4.f32 [%0], {%1, %2, %3, %4};"
                 :: "l"(p), "f"(m.x), "f"(m.y), "f"(m.z), "f"(m.w)
                 : "memory");
}

// ---------------- kernel 1/2: proj (+ fused zeroing on first launch) ----------------
__global__ void proj_kernel(const float* __restrict__ h_in,
                            const float* __restrict__ w_in,
                            float* __restrict__ h_out,
                            const int* __restrict__ kptr,
                            int do_zero) {
    int idx = blockIdx.x * blockDim.x + threadIdx.x;

    if (do_zero) {   // fold accumulator zeroing into the first proj launch
        float4 z = make_float4(0.f, 0.f, 0.f, 0.f);
        if (idx < NN * DN / 4) {
            reinterpret_cast<float4*>(g_user_msg)[idx] = z;
            reinterpret_cast<float4*>(g_item_msg)[idx] = z;
        }
        if (idx < NN / 4) {
            reinterpret_cast<float4*>(g_norm_u)[idx] = z;
            reinterpret_cast<float4*>(g_norm_i)[idx] = z;
        }
    }

    if (idx >= R * NN) return;
    int r = idx / NN, n = idx % NN;
    int kk = *kptr;

    const float* h = h_in + ((size_t)(kk * R + r) * NN + n) * DN;
    const float* W = w_in + r * DN * DN;
    float* out = h_out + ((size_t)r * NN + n) * DN;

    float x[DN];
#pragma unroll
    for (int i = 0; i < 4; i++) {
        float4 t = reinterpret_cast<const float4*>(h)[i];
        x[4*i+0] = t.x; x[4*i+1] = t.y; x[4*i+2] = t.z; x[4*i+3] = t.w;
    }
#pragma unroll
    for (int o = 0; o < DN; o++) {
        float acc = 0.f;
#pragma unroll
        for (int d = 0; d < DN; d++) acc += x[d] * __ldg(&W[o * DN + d]);
        out[o] = acc;
    }
}

// ---------------- kernel 3: blend-lite (4 edges/warp, 8 lanes/edge) ----------------
__global__ __launch_bounds__(256)
void blend_kernel(const float* __restrict__ user_h,
                  const float* __restrict__ item_h,
                  const float* __restrict__ user_hsum,
                  const float* __restrict__ item_hsum,
                  const float* __restrict__ review_feat,
                  const float* __restrict__ prototypes,
                  const float* __restrict__ eta,
                  const int* __restrict__ edge_src,
                  const int* __restrict__ edge_dst,
                  const int* __restrict__ kptr) {
    __shared__ float4 sproto[NF * DR / 4];   // 64 float4
    int tid = threadIdx.x;
    int r = blockIdx.y;
    if (tid < 64) sproto[tid] = reinterpret_cast<const float4*>(prototypes)[tid];
    __syncthreads();

    int warp = tid >> 5, lane = tid & 31, g = lane >> 3, sub = lane & 7;
    int e = (blockIdx.x * 8 + warp) * 4 + g;
    bool valid = e < E;
    int ec = valid ? e : E - 1;
    int kk = *kptr;
    int id = r * E + ec;
    int src = edge_src[id];
    int dst = edge_dst[id];

    // ---- sim_all denominator (hsum, 64 floats each side) ----
    const float4* ra = reinterpret_cast<const float4*>(user_hsum + ((size_t)r * NN + src) * (NF * DN));
    const float4* ca = reinterpret_cast<const float4*>(item_hsum + ((size_t)r * NN + dst) * (NF * DN));
    float p = dot4(ra[2 * sub], ca[2 * sub]) + dot4(ra[2 * sub + 1], ca[2 * sub + 1]);
    p += __shfl_xor_sync(0xffffffffu, p, 1);        // full dot for factor f = sub/2
    float ex = __expf(2.f * p);
    ex += __shfl_xor_sync(0xffffffffu, ex, 2);
    ex += __shfl_xor_sync(0xffffffffu, ex, 4);
    float denom_sim = ex;                           // each f counted once

    // ---- cosine sim (lanes sub<4 of each group) ----
    float uu = 0.f, vv = 0.f, uv = 0.f;
    if (sub < 4) {
        float4 a = reinterpret_cast<const float4*>(user_h + ((size_t)(kk * R + r) * NN + src) * DN)[sub];
        float4 b = reinterpret_cast<const float4*>(item_h + ((size_t)(kk * R + r) * NN + dst) * DN)[sub];
        uu = dot4(a, a); vv = dot4(b, b); uv = dot4(a, b);
    }
    uu += __shfl_xor_sync(0xffffffffu, uu, 1); uu += __shfl_xor_sync(0xffffffffu, uu, 2);
    vv += __shfl_xor_sync(0xffffffffu, vv, 1); vv += __shfl_xor_sync(0xffffffffu, vv, 2);
    uv += __shfl_xor_sync(0xffffffffu, uv, 1); uv += __shfl_xor_sync(0xffffffffu, uv, 2);

    // ---- anchors: stream rf row (256 floats), 8-lane-coalesced ----
    const float4* rf4 = reinterpret_cast<const float4*>(review_feat + (size_t)id * (NF * DR));
    float af[4] = {0.f, 0.f, 0.f, 0.f};
#pragma unroll
    for (int j = 0; j < 8; j++) {
        float4 q = rf4[sub + 8 * j];
        af[j >> 1] += dot4(q, sproto[sub + 8 * j]);
    }
#pragma unroll
    for (int o = 1; o < 8; o <<= 1) {
        af[0] += __shfl_xor_sync(0xffffffffu, af[0], o);
        af[1] += __shfl_xor_sync(0xffffffffu, af[1], o);
        af[2] += __shfl_xor_sync(0xffffffffu, af[2], o);
        af[3] += __shfl_xor_sync(0xffffffffu, af[3], o);
    }

    // ---- blended weight (lane sub==0 of each group) ----
    if (sub == 0 && valid) {
        float nu = fmaxf(sqrtf(uu), 1e-12f);
        float nv = fmaxf(sqrtf(vv), 1e-12f);
        float sim_k = 2.f * uv / (nu * nv);
        float exp_sim = __expf(sim_k) / denom_sim;

        float a0 = 2.f * af[0], a1 = 2.f * af[1], a2 = 2.f * af[2], a3 = 2.f * af[3];
        float denom_a = __expf(a0) + __expf(a1) + __expf(a2) + __expf(a3);
        float ak = (kk == 0) ? a0 : (kk == 1) ? a1 : (kk == 2) ? a2 : a3;
        float exp_anchor = __expf(ak) / denom_a;

        float gs = 1.f / (1.f + __expf(-eta[id]));
        float bl = gs * exp_anchor + (1.f - gs) * exp_sim;

        g_blended[id] = bl;
        atomicAdd(&g_norm_u[src], bl);
        atomicAdd(&g_norm_i[dst], bl);
    }
}

// ---------------- kernel 4: tiled GEMM + fused normalize/gather/scatter ----------------
// 256 threads, 128 edges/block. Each thread: 2 edges x 8 outputs.
__global__ __launch_bounds__(256)
void gemm_scatter_kernel(const float* __restrict__ review_feat,
                         const float* __restrict__ rw_fwd,
                         const float* __restrict__ rw_rev,
                         const int* __restrict__ edge_src,
                         const int* __restrict__ edge_dst,
                         const int* __restrict__ kptr,
                         float* __restrict__ out_int_dist) {
    __shared__ float4 sW[32 * 16];     // rows 0-15 Wf, 16-31 Wr
    __shared__ float4 sX[16 * 129];    // transposed X: [d4][edge], pitch 129
    __shared__ float  sw_s[TILE_E];
    __shared__ int    ssrc[TILE_E];
    __shared__ int    sdst[TILE_E];

    int r = blockIdx.y;
    int tid = threadIdx.x;
    int e0 = blockIdx.x * TILE_E;
    int kk = *kptr;

    // stage W (stacked): 2 float4 per thread
    {
        const float4* wf4 = reinterpret_cast<const float4*>(rw_fwd + r * DN * DR);
        const float4* wr4 = reinterpret_cast<const float4*>(rw_rev + r * DN * DR);
        for (int i = tid; i < 512; i += 256)
            sW[i] = (i < 256) ? wf4[i] : wr4[i - 256];
    }
    // stage X transposed (coalesced gmem): 16 rows per pass, 8 passes
    {
        int d4 = tid & 15, erow = tid >> 4;
#pragma unroll
        for (int pss = 0; pss < 8; pss++) {
            int e = erow + 16 * pss;
            int ge = e0 + e;
            float4 v = make_float4(0.f, 0.f, 0.f, 0.f);
            if (ge < E)
                v = reinterpret_cast<const float4*>(review_feat)[
                        ((size_t)(r * E + ge) * NF + kk) * (DR / 4) + d4];
            sX[d4 * 129 + e] = v;
        }
    }
    // per-edge normalized weight + int_dist (threads 0-127)
    if (tid < TILE_E) {
        int ge = e0 + tid;
        float w = 0.f; int s = 0, d = 0;
        if (ge < E) {
            int id = r * E + ge;
            s = edge_src[id]; d = edge_dst[id];
            w = g_blended[id] * rsqrtf(g_norm_u[s] * g_norm_i[d]);
            out_int_dist[id] = w;
        }
        sw_s[tid] = w; ssrc[tid] = s; sdst[tid] = d;
    }
    __syncthreads();

    int eq = tid & 31;
    int oo = (tid >> 5) & 3;   // output octet (uniform per warp)
    int eh = tid >> 7;         // edge half: 0 -> edges eq, eq+32 ; 1 -> eq+64, eq+96
    float acc[2][8];
#pragma unroll
    for (int j = 0; j < 2; j++)
#pragma unroll
        for (int o = 0; o < 8; o++) acc[j][o] = 0.f;

    const float4* wbase = sW + (8 * oo) * 16;
#pragma unroll
    for (int d4 = 0; d4 < 16; d4++) {
        float4 w0 = wbase[0 * 16 + d4], w1 = wbase[1 * 16 + d4];
        float4 w2 = wbase[2 * 16 + d4], w3 = wbase[3 * 16 + d4];
        float4 w4 = wbase[4 * 16 + d4], w5 = wbase[5 * 16 + d4];
        float4 w6 = wbase[6 * 16 + d4], w7 = wbase[7 * 16 + d4];
#pragma unroll
        for (int j = 0; j < 2; j++) {
            float4 x = sX[d4 * 129 + eq + 32 * (2 * eh + j)];
            acc[j][0] += dot4(x, w0); acc[j][1] += dot4(x, w1);
            acc[j][2] += dot4(x, w2); acc[j][3] += dot4(x, w3);
            acc[j][4] += dot4(x, w4); acc[j][5] += dot4(x, w5);
            acc[j][6] += dot4(x, w6); acc[j][7] += dot4(x, w7);
        }
    }

    bool fwd = oo < 2;      // outputs 0-15 = m_fwd, 16-31 = m_rev
    int half = oo & 1;      // which 8-float half of the 16-dim message
#pragma unroll
    for (int j = 0; j < 2; j++) {
        int et = eq + 32 * (2 * eh + j);
        int ge = e0 + et;
        if (ge >= E) continue;
        float wv = sw_s[et];
        int s = ssrc[et], d = sdst[et];
        const float4* h4 = reinterpret_cast<const float4*>(
            fwd ? g_hu + ((size_t)r * NN + s) * DN
                : g_hi + ((size_t)r * NN + d) * DN) + 2 * half;
        float* tgt = (fwd ? g_item_msg + (size_t)d * DN
                          : g_user_msg + (size_t)s * DN) + 8 * half;
        float4 h0 = __ldg(h4), h1 = __ldg(h4 + 1);
        red_add_v4(tgt, make_float4((acc[j][0] + h0.x) * wv, (acc[j][1] + h0.y) * wv,
                                    (acc[j][2] + h0.z) * wv, (acc[j][3] + h0.w) * wv));
        red_add_v4(tgt + 4, make_float4((acc[j][4] + h1.x) * wv, (acc[j][5] + h1.y) * wv,
                                        (acc[j][6] + h1.z) * wv, (acc[j][7] + h1.w) * wv));
    }
}

// ---------------- kernel 5: leaky_relu + FC for users and items ----------------
__global__ void fc_kernel(const float* __restrict__ ufc_w, const float* __restrict__ ufc_b,
                          const float* __restrict__ ifc_w, const float* __restrict__ ifc_b,
                          float* __restrict__ out) {
    __shared__ float sW[2][DO * DN];
    __shared__ float sB[2][DO];
    int tid = threadIdx.x;   // 256
    for (int i = tid; i < DO * DN; i += 256) { sW[0][i] = ufc_w[i]; sW[1][i] = ifc_w[i]; }
    if (tid < DO) { sB[0][tid] = ufc_b[tid]; sB[1][tid] = ifc_b[tid]; }
    __syncthreads();

    int node = blockIdx.x * (256 / DO) + tid / DO;
    int o = tid % DO;
    if (node >= 2 * NN) return;
    int side = node >= NN;
    int n = side ? node - NN : node;
    const float* msg = (side ? g_item_msg : g_user_msg) + (size_t)n * DN;

    float acc = sB[side][o];
#pragma unroll
    for (int d = 0; d < DN; d++) {
        float m = msg[d];
        m = (m >= 0.f) ? m : 0.1f * m;
        acc += m * sW[side][o * DN + d];
    }
    out[(size_t)node * DO + o] = acc;
}

// ---------------- launch ----------------
extern "C" void kernel_launch(void* const* d_in, const int* in_sizes, int n_in,
                              void* d_out, int out_size) {
    const float* user_h      = (const float*)d_in[0];
    const float* item_h      = (const float*)d_in[1];
    const float* user_hsum   = (const float*)d_in[2];
    const float* item_hsum   = (const float*)d_in[3];
    const float* review_feat = (const float*)d_in[4];
    const float* prototypes  = (const float*)d_in[5];
    const float* eta         = (const float*)d_in[6];
    const float* node_w_fwd  = (const float*)d_in[7];
    const float* review_w_fwd= (const float*)d_in[8];
    const float* node_w_rev  = (const float*)d_in[9];
    const float* review_w_rev= (const float*)d_in[10];
    const float* ufc_w       = (const float*)d_in[11];
    const float* ufc_b       = (const float*)d_in[12];
    const float* ifc_w       = (const float*)d_in[13];
    const float* ifc_b       = (const float*)d_in[14];
    const int*   edge_src    = (const int*)d_in[15];
    const int*   edge_dst    = (const int*)d_in[16];
    const int*   kptr        = (const int*)d_in[17];

    float* out = (float*)d_out;
    float* out_int = out + (size_t)2 * NN * DO;   // int_dist after ufeat+ifeat

    // launches 1, 2 (zeroing fused into launch 1)
    int gp = (R * NN + 255) / 256;
    float* g_hu_p; cudaGetSymbolAddress((void**)&g_hu_p, g_hu);
    float* g_hi_p; cudaGetSymbolAddress((void**)&g_hi_p, g_hi);
    proj_kernel<<<gp, 256>>>(user_h, node_w_fwd, g_hu_p, kptr, 1);
    proj_kernel<<<gp, 256>>>(item_h, node_w_rev, g_hi_p, kptr, 0);

    // launch 3: blend-lite
    dim3 gb((E + 31) / 32, R);   // 32 edges per 256-thread block
    blend_kernel<<<gb, 256>>>(user_h, item_h, user_hsum, item_hsum,
                              review_feat, prototypes, eta,
                              edge_src, edge_dst, kptr);

    // launch 4: fused GEMM + scatter (profiled slot)
    dim3 gg((E + TILE_E - 1) / TILE_E, R);
    gemm_scatter_kernel<<<gg, 256>>>(review_feat, review_w_fwd, review_w_rev,
                                     edge_src, edge_dst, kptr, out_int);

    // launch 5
    fc_kernel<<<(2 * NN * DO) / 256, 256>>>(ufc_w, ufc_b, ifc_w, ifc_b, out);
}

// round 11
// speedup vs baseline: 2.2218x; 1.0625x over previous
#include <cuda_runtime.h>
#include <cstdint>

#define R  5
#define E  50000
#define NN 20000      // NU == NI
#define NF 4
#define DN 16
#define DR 64
#define DO 64
#define TILE_E 128
// TAU = 0.5 -> 1/TAU = 2.0f

// ---------------- scratch (device globals; no allocation) ----------------
__device__ __align__(16) float g_blended[R * E];
__device__ __align__(16) float g_norm_u[NN];
__device__ __align__(16) float g_norm_i[NN];
__device__ __align__(16) float g_hu[R * NN * DN];
__device__ __align__(16) float g_hi[R * NN * DN];
__device__ __align__(16) float g_user_msg[NN * DN];
__device__ __align__(16) float g_item_msg[NN * DN];

__device__ __forceinline__ float dot4(float4 a, float4 b) {
    return a.x * b.x + a.y * b.y + a.z * b.z + a.w * b.w;
}

// vector global reduction (sm_90+): 4 floats in one RED
__device__ __forceinline__ void red_add_v4(float* p, float4 m) {
    asm volatile("red.global.add.v4.f32 [%0], {%1, %2, %3, %4};"
                 :: "l"(p), "f"(m.x), "f"(m.y), "f"(m.z), "f"(m.w)
                 : "memory");
}

// LDS.128 delivering two packed f32x2 (no pack MOVs)
#define LDS_V2_U64(lo, hi, addr) \
    asm("ld.shared.v2.b64 {%0, %1}, [%2];" : "=l"(lo), "=l"(hi) : "r"(addr))

// packed dual FMA: acc.{lo,hi} += a.{lo,hi} * b.{lo,hi}
__device__ __forceinline__ void ffma2(uint64_t& acc, uint64_t a, uint64_t b) {
    asm("fma.rn.f32x2 %0, %1, %2, %0;" : "+l"(acc) : "l"(a), "l"(b));
}

__device__ __forceinline__ float hsum2(uint64_t acc) {
    float lo, hi;
    asm("mov.b64 {%0, %1}, %2;" : "=f"(lo), "=f"(hi) : "l"(acc));
    return lo + hi;
}

// ---------------- kernel 1: proj both sides (+ fused zeroing) ----------------
__global__ void proj_kernel(const float* __restrict__ user_h,
                            const float* __restrict__ item_h,
                            const float* __restrict__ w_fwd,
                            const float* __restrict__ w_rev,
                            const int* __restrict__ kptr) {
    int idx = blockIdx.x * blockDim.x + threadIdx.x;
    int side = blockIdx.y;

    if (side == 0) {   // fold accumulator zeroing into side-0 blocks
        float4 z = make_float4(0.f, 0.f, 0.f, 0.f);
        if (idx < NN * DN / 4) {
            reinterpret_cast<float4*>(g_user_msg)[idx] = z;
            reinterpret_cast<float4*>(g_item_msg)[idx] = z;
        }
        if (idx < NN / 4) {
            reinterpret_cast<float4*>(g_norm_u)[idx] = z;
            reinterpret_cast<float4*>(g_norm_i)[idx] = z;
        }
    }

    if (idx >= R * NN) return;
    int r = idx / NN, n = idx % NN;
    int kk = *kptr;

    const float* h = (side ? item_h : user_h) + ((size_t)(kk * R + r) * NN + n) * DN;
    const float* W = (side ? w_rev : w_fwd) + r * DN * DN;
    float* out = (side ? g_hi : g_hu) + ((size_t)r * NN + n) * DN;

    float x[DN];
#pragma unroll
    for (int i = 0; i < 4; i++) {
        float4 t = reinterpret_cast<const float4*>(h)[i];
        x[4*i+0] = t.x; x[4*i+1] = t.y; x[4*i+2] = t.z; x[4*i+3] = t.w;
    }
#pragma unroll
    for (int o = 0; o < DN; o++) {
        float acc = 0.f;
#pragma unroll
        for (int d = 0; d < DN; d++) acc += x[d] * __ldg(&W[o * DN + d]);
        out[o] = acc;
    }
}

// ---------------- kernel 2: blend-lite (4 edges/warp, 8 lanes/edge) ----------------
__global__ __launch_bounds__(256)
void blend_kernel(const float* __restrict__ user_h,
                  const float* __restrict__ item_h,
                  const float* __restrict__ user_hsum,
                  const float* __restrict__ item_hsum,
                  const float* __restrict__ review_feat,
                  const float* __restrict__ prototypes,
                  const float* __restrict__ eta,
                  const int* __restrict__ edge_src,
                  const int* __restrict__ edge_dst,
                  const int* __restrict__ kptr) {
    __shared__ float4 sproto[NF * DR / 4];   // 64 float4
    int tid = threadIdx.x;
    int r = blockIdx.y;
    if (tid < 64) sproto[tid] = reinterpret_cast<const float4*>(prototypes)[tid];
    __syncthreads();

    int warp = tid >> 5, lane = tid & 31, g = lane >> 3, sub = lane & 7;
    int e = (blockIdx.x * 8 + warp) * 4 + g;
    bool valid = e < E;
    int ec = valid ? e : E - 1;
    int kk = *kptr;
    int id = r * E + ec;
    int src = edge_src[id];
    int dst = edge_dst[id];

    // ---- sim_all denominator (hsum, 64 floats each side) ----
    const float4* ra = reinterpret_cast<const float4*>(user_hsum + ((size_t)r * NN + src) * (NF * DN));
    const float4* ca = reinterpret_cast<const float4*>(item_hsum + ((size_t)r * NN + dst) * (NF * DN));
    float p = dot4(ra[2 * sub], ca[2 * sub]) + dot4(ra[2 * sub + 1], ca[2 * sub + 1]);
    p += __shfl_xor_sync(0xffffffffu, p, 1);        // full dot for factor f = sub/2
    float ex = __expf(2.f * p);
    ex += __shfl_xor_sync(0xffffffffu, ex, 2);
    ex += __shfl_xor_sync(0xffffffffu, ex, 4);
    float denom_sim = ex;                           // each f counted once

    // ---- cosine sim (lanes sub<4 of each group) ----
    float uu = 0.f, vv = 0.f, uv = 0.f;
    if (sub < 4) {
        float4 a = reinterpret_cast<const float4*>(user_h + ((size_t)(kk * R + r) * NN + src) * DN)[sub];
        float4 b = reinterpret_cast<const float4*>(item_h + ((size_t)(kk * R + r) * NN + dst) * DN)[sub];
        uu = dot4(a, a); vv = dot4(b, b); uv = dot4(a, b);
    }
    uu += __shfl_xor_sync(0xffffffffu, uu, 1); uu += __shfl_xor_sync(0xffffffffu, uu, 2);
    vv += __shfl_xor_sync(0xffffffffu, vv, 1); vv += __shfl_xor_sync(0xffffffffu, vv, 2);
    uv += __shfl_xor_sync(0xffffffffu, uv, 1); uv += __shfl_xor_sync(0xffffffffu, uv, 2);

    // ---- anchors: stream rf row (256 floats), 8-lane-coalesced ----
    const float4* rf4 = reinterpret_cast<const float4*>(review_feat + (size_t)id * (NF * DR));
    float af[4] = {0.f, 0.f, 0.f, 0.f};
#pragma unroll
    for (int j = 0; j < 8; j++) {
        float4 q = rf4[sub + 8 * j];
        af[j >> 1] += dot4(q, sproto[sub + 8 * j]);
    }
#pragma unroll
    for (int o = 1; o < 8; o <<= 1) {
        af[0] += __shfl_xor_sync(0xffffffffu, af[0], o);
        af[1] += __shfl_xor_sync(0xffffffffu, af[1], o);
        af[2] += __shfl_xor_sync(0xffffffffu, af[2], o);
        af[3] += __shfl_xor_sync(0xffffffffu, af[3], o);
    }

    // ---- blended weight (lane sub==0 of each group) ----
    if (sub == 0 && valid) {
        float nu = fmaxf(sqrtf(uu), 1e-12f);
        float nv = fmaxf(sqrtf(vv), 1e-12f);
        float sim_k = 2.f * uv / (nu * nv);
        float exp_sim = __expf(sim_k) / denom_sim;

        float a0 = 2.f * af[0], a1 = 2.f * af[1], a2 = 2.f * af[2], a3 = 2.f * af[3];
        float denom_a = __expf(a0) + __expf(a1) + __expf(a2) + __expf(a3);
        float ak = (kk == 0) ? a0 : (kk == 1) ? a1 : (kk == 2) ? a2 : a3;
        float exp_anchor = __expf(ak) / denom_a;

        float gs = 1.f / (1.f + __expf(-eta[id]));
        float bl = gs * exp_anchor + (1.f - gs) * exp_sim;

        g_blended[id] = bl;
        atomicAdd(&g_norm_u[src], bl);
        atomicAdd(&g_norm_i[dst], bl);
    }
}

// ---------------- kernel 3: tiled GEMM (packed f32x2) + fused scatter ----------------
// 256 threads, 128 edges/block. Thread: 2 edges x 8 outputs, packed-K FMA.
__global__ __launch_bounds__(256)
void gemm_scatter_kernel(const float* __restrict__ review_feat,
                         const float* __restrict__ rw_fwd,
                         const float* __restrict__ rw_rev,
                         const int* __restrict__ edge_src,
                         const int* __restrict__ edge_dst,
                         const int* __restrict__ kptr,
                         float* __restrict__ out_int_dist) {
    __shared__ float4 sW[32 * 16];     // rows 0-15 Wf, 16-31 Wr
    __shared__ float4 sX[16 * 129];    // transposed X: [d4][edge], pitch 129
    __shared__ float  sw_s[TILE_E];
    __shared__ int    ssrc[TILE_E];
    __shared__ int    sdst[TILE_E];

    int r = blockIdx.y;
    int tid = threadIdx.x;
    int e0 = blockIdx.x * TILE_E;
    int kk = *kptr;

    // stage W (stacked)
    {
        const float4* wf4 = reinterpret_cast<const float4*>(rw_fwd + r * DN * DR);
        const float4* wr4 = reinterpret_cast<const float4*>(rw_rev + r * DN * DR);
        for (int i = tid; i < 512; i += 256)
            sW[i] = (i < 256) ? wf4[i] : wr4[i - 256];
    }
    // stage X transposed (coalesced gmem)
    {
        int d4 = tid & 15, erow = tid >> 4;
#pragma unroll
        for (int pss = 0; pss < 8; pss++) {
            int e = erow + 16 * pss;
            int ge = e0 + e;
            float4 v = make_float4(0.f, 0.f, 0.f, 0.f);
            if (ge < E)
                v = reinterpret_cast<const float4*>(review_feat)[
                        ((size_t)(r * E + ge) * NF + kk) * (DR / 4) + d4];
            sX[d4 * 129 + e] = v;
        }
    }
    // per-edge normalized weight + int_dist (threads 0-127)
    if (tid < TILE_E) {
        int ge = e0 + tid;
        float w = 0.f; int s = 0, d = 0;
        if (ge < E) {
            int id = r * E + ge;
            s = edge_src[id]; d = edge_dst[id];
            w = g_blended[id] * rsqrtf(g_norm_u[s] * g_norm_i[d]);
            out_int_dist[id] = w;
        }
        sw_s[tid] = w; ssrc[tid] = s; sdst[tid] = d;
    }
    __syncthreads();

    uint32_t sW_b = (uint32_t)__cvta_generic_to_shared(sW);
    uint32_t sX_b = (uint32_t)__cvta_generic_to_shared(sX);

    int eq = tid & 31;
    int oo = (tid >> 5) & 3;   // output octet (uniform per warp)
    int eh = tid >> 7;         // edge half
    uint64_t acc[2][8] = {};   // packed {even,odd} partial sums

#pragma unroll
    for (int d4 = 0; d4 < 16; d4++) {
        uint64_t xl[2], xh[2];
        LDS_V2_U64(xl[0], xh[0], sX_b + (uint32_t)(d4 * 129 + eq + 32 * (2 * eh + 0)) * 16u);
        LDS_V2_U64(xl[1], xh[1], sX_b + (uint32_t)(d4 * 129 + eq + 32 * (2 * eh + 1)) * 16u);
#pragma unroll
        for (int og = 0; og < 2; og++) {
            uint64_t wl[4], wh[4];
#pragma unroll
            for (int o = 0; o < 4; o++)
                LDS_V2_U64(wl[o], wh[o],
                           sW_b + (uint32_t)(((8 * oo + 4 * og + o) * 16 + d4)) * 16u);
#pragma unroll
            for (int j = 0; j < 2; j++)
#pragma unroll
                for (int o = 0; o < 4; o++) {
                    ffma2(acc[j][4 * og + o], xl[j], wl[o]);
                    ffma2(acc[j][4 * og + o], xh[j], wh[o]);
                }
        }
    }

    bool fwd = oo < 2;      // outputs 0-15 = m_fwd, 16-31 = m_rev
    int half = oo & 1;      // which 8-float half of the 16-dim message
#pragma unroll
    for (int j = 0; j < 2; j++) {
        int et = eq + 32 * (2 * eh + j);
        int ge = e0 + et;
        if (ge >= E) continue;
        float a[8];
#pragma unroll
        for (int o = 0; o < 8; o++) a[o] = hsum2(acc[j][o]);
        float wv = sw_s[et];
        int s = ssrc[et], d = sdst[et];
        const float4* h4 = reinterpret_cast<const float4*>(
            fwd ? g_hu + ((size_t)r * NN + s) * DN
                : g_hi + ((size_t)r * NN + d) * DN) + 2 * half;
        float* tgt = (fwd ? g_item_msg + (size_t)d * DN
                          : g_user_msg + (size_t)s * DN) + 8 * half;
        float4 h0 = __ldg(h4), h1 = __ldg(h4 + 1);
        red_add_v4(tgt, make_float4((a[0] + h0.x) * wv, (a[1] + h0.y) * wv,
                                    (a[2] + h0.z) * wv, (a[3] + h0.w) * wv));
        red_add_v4(tgt + 4, make_float4((a[4] + h1.x) * wv, (a[5] + h1.y) * wv,
                                        (a[6] + h1.z) * wv, (a[7] + h1.w) * wv));
    }
}

// ---------------- kernel 4: leaky_relu + FC for users and items ----------------
__global__ void fc_kernel(const float* __restrict__ ufc_w, const float* __restrict__ ufc_b,
                          const float* __restrict__ ifc_w, const float* __restrict__ ifc_b,
                          float* __restrict__ out) {
    __shared__ float sW[2][DO * DN];
    __shared__ float sB[2][DO];
    int tid = threadIdx.x;   // 256
    for (int i = tid; i < DO * DN; i += 256) { sW[0][i] = ufc_w[i]; sW[1][i] = ifc_w[i]; }
    if (tid < DO) { sB[0][tid] = ufc_b[tid]; sB[1][tid] = ifc_b[tid]; }
    __syncthreads();

    int node = blockIdx.x * (256 / DO) + tid / DO;
    int o = tid % DO;
    if (node >= 2 * NN) return;
    int side = node >= NN;
    int n = side ? node - NN : node;
    const float* msg = (side ? g_item_msg : g_user_msg) + (size_t)n * DN;

    float acc = sB[side][o];
#pragma unroll
    for (int d = 0; d < DN; d++) {
        float m = msg[d];
        m = (m >= 0.f) ? m : 0.1f * m;
        acc += m * sW[side][o * DN + d];
    }
    out[(size_t)node * DO + o] = acc;
}

// ---------------- launch ----------------
extern "C" void kernel_launch(void* const* d_in, const int* in_sizes, int n_in,
                              void* d_out, int out_size) {
    const float* user_h      = (const float*)d_in[0];
    const float* item_h      = (const float*)d_in[1];
    const float* user_hsum   = (const float*)d_in[2];
    const float* item_hsum   = (const float*)d_in[3];
    const float* review_feat = (const float*)d_in[4];
    const float* prototypes  = (const float*)d_in[5];
    const float* eta         = (const float*)d_in[6];
    const float* node_w_fwd  = (const float*)d_in[7];
    const float* review_w_fwd= (const float*)d_in[8];
    const float* node_w_rev  = (const float*)d_in[9];
    const float* review_w_rev= (const float*)d_in[10];
    const float* ufc_w       = (const float*)d_in[11];
    const float* ufc_b       = (const float*)d_in[12];
    const float* ifc_w       = (const float*)d_in[13];
    const float* ifc_b       = (const float*)d_in[14];
    const int*   edge_src    = (const int*)d_in[15];
    const int*   edge_dst    = (const int*)d_in[16];
    const int*   kptr        = (const int*)d_in[17];

    float* out = (float*)d_out;
    float* out_int = out + (size_t)2 * NN * DO;   // int_dist after ufeat+ifeat

    // launch 1: proj both sides (+ zeroing)
    dim3 gp((R * NN + 255) / 256, 2);
    proj_kernel<<<gp, 256>>>(user_h, item_h, node_w_fwd, node_w_rev, kptr);

    // launch 2: blend-lite
    dim3 gb((E + 31) / 32, R);   // 32 edges per 256-thread block
    blend_kernel<<<gb, 256>>>(user_h, item_h, user_hsum, item_hsum,
                              review_feat, prototypes, eta,
                              edge_src, edge_dst, kptr);

    // launch 3: fused GEMM + scatter (packed f32x2)
    dim3 gg((E + TILE_E - 1) / TILE_E, R);
    gemm_scatter_kernel<<<gg, 256>>>(review_feat, review_w_fwd, review_w_rev,
                                     edge_src, edge_dst, kptr, out_int);

    // launch 4
    fc_kernel<<<(2 * NN * DO) / 256, 256>>>(ufc_w, ufc_b, ifc_w, ifc_b, out);
}

// round 13
// speedup vs baseline: 2.5830x; 1.1626x over previous
#include <cuda_runtime.h>
#include <cstdint>

#define R  5
#define E  50000
#define NN 20000      // NU == NI
#define NF 4
#define DN 16
#define DR 64
#define DO 64
#define TILE_E 128
// TAU = 0.5 -> 1/TAU = 2.0f

// ---------------- scratch (device globals; no allocation) ----------------
__device__ __align__(16) float g_blended[R * E];
__device__ __align__(16) float g_norm_u[NN];
__device__ __align__(16) float g_norm_i[NN];
__device__ __align__(16) float g_hu[R * NN * DN];
__device__ __align__(16) float g_hi[R * NN * DN];
__device__ __align__(16) float g_user_msg[NN * DN];
__device__ __align__(16) float g_item_msg[NN * DN];

__device__ __forceinline__ float dot4(float4 a, float4 b) {
    return a.x * b.x + a.y * b.y + a.z * b.z + a.w * b.w;
}

// vector global reduction (sm_90+): 4 floats in one RED
__device__ __forceinline__ void red_add_v4(float* p, float4 m) {
    asm volatile("red.global.add.v4.f32 [%0], {%1, %2, %3, %4};"
                 :: "l"(p), "f"(m.x), "f"(m.y), "f"(m.z), "f"(m.w)
                 : "memory");
}

// LDS.128 delivering two packed f32x2 (no pack MOVs)
#define LDS_V2_U64(lo, hi, addr) \
    asm("ld.shared.v2.b64 {%0, %1}, [%2];" : "=l"(lo), "=l"(hi) : "r"(addr))

// packed dual FMA: acc.{lo,hi} += a.{lo,hi} * b.{lo,hi}
__device__ __forceinline__ void ffma2(uint64_t& acc, uint64_t a, uint64_t b) {
    asm("fma.rn.f32x2 %0, %1, %2, %0;" : "+l"(acc) : "l"(a), "l"(b));
}

__device__ __forceinline__ float hsum2(uint64_t acc) {
    float lo, hi;
    asm("mov.b64 {%0, %1}, %2;" : "=f"(lo), "=f"(hi) : "l"(acc));
    return lo + hi;
}

// ---------------- kernel 1: proj both sides (+ fused zeroing) ----------------
__global__ void proj_kernel(const float* __restrict__ user_h,
                            const float* __restrict__ item_h,
                            const float* __restrict__ w_fwd,
                            const float* __restrict__ w_rev,
                            const int* __restrict__ kptr) {
    int idx = blockIdx.x * blockDim.x + threadIdx.x;
    int side = blockIdx.y;

    if (side == 0) {   // fold accumulator zeroing into side-0 blocks
        float4 z = make_float4(0.f, 0.f, 0.f, 0.f);
        if (idx < NN * DN / 4) {
            reinterpret_cast<float4*>(g_user_msg)[idx] = z;
            reinterpret_cast<float4*>(g_item_msg)[idx] = z;
        }
        if (idx < NN / 4) {
            reinterpret_cast<float4*>(g_norm_u)[idx] = z;
            reinterpret_cast<float4*>(g_norm_i)[idx] = z;
        }
    }

    if (idx >= R * NN) return;
    int r = idx / NN, n = idx % NN;
    int kk = *kptr;

    const float* h = (side ? item_h : user_h) + ((size_t)(kk * R + r) * NN + n) * DN;
    const float* W = (side ? w_rev : w_fwd) + r * DN * DN;
    float* out = (side ? g_hi : g_hu) + ((size_t)r * NN + n) * DN;

    float x[DN];
#pragma unroll
    for (int i = 0; i < 4; i++) {
        float4 t = reinterpret_cast<const float4*>(h)[i];
        x[4*i+0] = t.x; x[4*i+1] = t.y; x[4*i+2] = t.z; x[4*i+3] = t.w;
    }
#pragma unroll
    for (int o = 0; o < DN; o++) {
        float acc = 0.f;
#pragma unroll
        for (int d = 0; d < DN; d++) acc += x[d] * __ldg(&W[o * DN + d]);
        out[o] = acc;
    }
}

// ---------------- kernel 2: blend-lite (4 edges/warp, 8 lanes/edge) ----------------
__global__ __launch_bounds__(256)
void blend_kernel(const float* __restrict__ user_h,
                  const float* __restrict__ item_h,
                  const float* __restrict__ user_hsum,
                  const float* __restrict__ item_hsum,
                  const float* __restrict__ review_feat,
                  const float* __restrict__ prototypes,
                  const float* __restrict__ eta,
                  const int* __restrict__ edge_src,
                  const int* __restrict__ edge_dst,
                  const int* __restrict__ kptr) {
    __shared__ float4 sproto[NF * DR / 4];   // 64 float4
    int tid = threadIdx.x;
    int r = blockIdx.y;
    if (tid < 64) sproto[tid] = reinterpret_cast<const float4*>(prototypes)[tid];
    __syncthreads();

    int warp = tid >> 5, lane = tid & 31, g = lane >> 3, sub = lane & 7;
    int e = (blockIdx.x * 8 + warp) * 4 + g;
    bool valid = e < E;
    int ec = valid ? e : E - 1;
    int kk = *kptr;
    int id = r * E + ec;
    int src = edge_src[id];
    int dst = edge_dst[id];

    // ---- sim_all denominator (hsum, 64 floats each side) ----
    const float4* ra = reinterpret_cast<const float4*>(user_hsum + ((size_t)r * NN + src) * (NF * DN));
    const float4* ca = reinterpret_cast<const float4*>(item_hsum + ((size_t)r * NN + dst) * (NF * DN));
    float p = dot4(ra[2 * sub], ca[2 * sub]) + dot4(ra[2 * sub + 1], ca[2 * sub + 1]);
    p += __shfl_xor_sync(0xffffffffu, p, 1);        // full dot for factor f = sub/2
    float ex = __expf(2.f * p);
    ex += __shfl_xor_sync(0xffffffffu, ex, 2);
    ex += __shfl_xor_sync(0xffffffffu, ex, 4);
    float denom_sim = ex;                           // each f counted once

    // ---- cosine sim (lanes sub<4 of each group) ----
    float uu = 0.f, vv = 0.f, uv = 0.f;
    if (sub < 4) {
        float4 a = reinterpret_cast<const float4*>(user_h + ((size_t)(kk * R + r) * NN + src) * DN)[sub];
        float4 b = reinterpret_cast<const float4*>(item_h + ((size_t)(kk * R + r) * NN + dst) * DN)[sub];
        uu = dot4(a, a); vv = dot4(b, b); uv = dot4(a, b);
    }
    uu += __shfl_xor_sync(0xffffffffu, uu, 1); uu += __shfl_xor_sync(0xffffffffu, uu, 2);
    vv += __shfl_xor_sync(0xffffffffu, vv, 1); vv += __shfl_xor_sync(0xffffffffu, vv, 2);
    uv += __shfl_xor_sync(0xffffffffu, uv, 1); uv += __shfl_xor_sync(0xffffffffu, uv, 2);

    // ---- anchors: stream rf row (256 floats), 8-lane-coalesced ----
    const float4* rf4 = reinterpret_cast<const float4*>(review_feat + (size_t)id * (NF * DR));
    float af[4] = {0.f, 0.f, 0.f, 0.f};
#pragma unroll
    for (int j = 0; j < 8; j++) {
        float4 q = rf4[sub + 8 * j];
        af[j >> 1] += dot4(q, sproto[sub + 8 * j]);
    }
#pragma unroll
    for (int o = 1; o < 8; o <<= 1) {
        af[0] += __shfl_xor_sync(0xffffffffu, af[0], o);
        af[1] += __shfl_xor_sync(0xffffffffu, af[1], o);
        af[2] += __shfl_xor_sync(0xffffffffu, af[2], o);
        af[3] += __shfl_xor_sync(0xffffffffu, af[3], o);
    }

    // ---- blended weight (lane sub==0 of each group) ----
    if (sub == 0 && valid) {
        float nu = fmaxf(sqrtf(uu), 1e-12f);
        float nv = fmaxf(sqrtf(vv), 1e-12f);
        float sim_k = 2.f * uv / (nu * nv);
        float exp_sim = __expf(sim_k) / denom_sim;

        float a0 = 2.f * af[0], a1 = 2.f * af[1], a2 = 2.f * af[2], a3 = 2.f * af[3];
        float denom_a = __expf(a0) + __expf(a1) + __expf(a2) + __expf(a3);
        float ak = (kk == 0) ? a0 : (kk == 1) ? a1 : (kk == 2) ? a2 : a3;
        float exp_anchor = __expf(ak) / denom_a;

        float gs = 1.f / (1.f + __expf(-eta[id]));
        float bl = gs * exp_anchor + (1.f - gs) * exp_sim;

        g_blended[id] = bl;
        atomicAdd(&g_norm_u[src], bl);
        atomicAdd(&g_norm_i[dst], bl);
    }
}

// ---------------- kernel 3: tiled GEMM (packed f32x2) + fused scatter ----------------
__global__ __launch_bounds__(256)
void gemm_scatter_kernel(const float* __restrict__ review_feat,
                         const float* __restrict__ rw_fwd,
                         const float* __restrict__ rw_rev,
                         const int* __restrict__ edge_src,
                         const int* __restrict__ edge_dst,
                         const int* __restrict__ kptr,
                         float* __restrict__ out_int_dist) {
    __shared__ float4 sW[32 * 16];     // rows 0-15 Wf, 16-31 Wr
    __shared__ float4 sX[16 * 129];    // transposed X: [d4][edge], pitch 129
    __shared__ float  sw_s[TILE_E];
    __shared__ int    ssrc[TILE_E];
    __shared__ int    sdst[TILE_E];

    int r = blockIdx.y;
    int tid = threadIdx.x;
    int e0 = blockIdx.x * TILE_E;
    int kk = *kptr;

    // stage W (stacked)
    {
        const float4* wf4 = reinterpret_cast<const float4*>(rw_fwd + r * DN * DR);
        const float4* wr4 = reinterpret_cast<const float4*>(rw_rev + r * DN * DR);
        for (int i = tid; i < 512; i += 256)
            sW[i] = (i < 256) ? wf4[i] : wr4[i - 256];
    }
    // stage X transposed (coalesced gmem)
    {
        int d4 = tid & 15, erow = tid >> 4;
#pragma unroll
        for (int pss = 0; pss < 8; pss++) {
            int e = erow + 16 * pss;
            int ge = e0 + e;
            float4 v = make_float4(0.f, 0.f, 0.f, 0.f);
            if (ge < E)
                v = reinterpret_cast<const float4*>(review_feat)[
                        ((size_t)(r * E + ge) * NF + kk) * (DR / 4) + d4];
            sX[d4 * 129 + e] = v;
        }
    }
    // per-edge normalized weight + int_dist (threads 0-127)
    if (tid < TILE_E) {
        int ge = e0 + tid;
        float w = 0.f; int s = 0, d = 0;
        if (ge < E) {
            int id = r * E + ge;
            s = edge_src[id]; d = edge_dst[id];
            w = g_blended[id] * rsqrtf(g_norm_u[s] * g_norm_i[d]);
            out_int_dist[id] = w;
        }
        sw_s[tid] = w; ssrc[tid] = s; sdst[tid] = d;
    }
    __syncthreads();

    uint32_t sW_b = (uint32_t)__cvta_generic_to_shared(sW);
    uint32_t sX_b = (uint32_t)__cvta_generic_to_shared(sX);

    int eq = tid & 31;
    int oo = (tid >> 5) & 3;   // output octet (uniform per warp)
    int eh = tid >> 7;         // edge half
    uint64_t acc[2][8] = {};   // packed {even,odd} partial sums

#pragma unroll
    for (int d4 = 0; d4 < 16; d4++) {
        uint64_t xl[2], xh[2];
        LDS_V2_U64(xl[0], xh[0], sX_b + (uint32_t)(d4 * 129 + eq + 32 * (2 * eh + 0)) * 16u);
        LDS_V2_U64(xl[1], xh[1], sX_b + (uint32_t)(d4 * 129 + eq + 32 * (2 * eh + 1)) * 16u);
#pragma unroll
        for (int og = 0; og < 2; og++) {
            uint64_t wl[4], wh[4];
#pragma unroll
            for (int o = 0; o < 4; o++)
                LDS_V2_U64(wl[o], wh[o],
                           sW_b + (uint32_t)(((8 * oo + 4 * og + o) * 16 + d4)) * 16u);
#pragma unroll
            for (int j = 0; j < 2; j++)
#pragma unroll
                for (int o = 0; o < 4; o++) {
                    ffma2(acc[j][4 * og + o], xl[j], wl[o]);
                    ffma2(acc[j][4 * og + o], xh[j], wh[o]);
                }
        }
    }

    bool fwd = oo < 2;      // outputs 0-15 = m_fwd, 16-31 = m_rev
    int half = oo & 1;      // which 8-float half of the 16-dim message
#pragma unroll
    for (int j = 0; j < 2; j++) {
        int et = eq + 32 * (2 * eh + j);
        int ge = e0 + et;
        if (ge >= E) continue;
        float a[8];
#pragma unroll
        for (int o = 0; o < 8; o++) a[o] = hsum2(acc[j][o]);
        float wv = sw_s[et];
        int s = ssrc[et], d = sdst[et];
        const float4* h4 = reinterpret_cast<const float4*>(
            fwd ? g_hu + ((size_t)r * NN + s) * DN
                : g_hi + ((size_t)r * NN + d) * DN) + 2 * half;
        float* tgt = (fwd ? g_item_msg + (size_t)d * DN
                          : g_user_msg + (size_t)s * DN) + 8 * half;
        float4 h0 = __ldg(h4), h1 = __ldg(h4 + 1);
        red_add_v4(tgt, make_float4((a[0] + h0.x) * wv, (a[1] + h0.y) * wv,
                                    (a[2] + h0.z) * wv, (a[3] + h0.w) * wv));
        red_add_v4(tgt + 4, make_float4((a[4] + h1.x) * wv, (a[5] + h1.y) * wv,
                                        (a[6] + h1.z) * wv, (a[7] + h1.w) * wv));
    }
}

// ---------------- kernel 4: leaky_relu + FC, tiled (64 nodes/block) ----------------
// Stage: coalesced msg load + leaky (once per element) -> smem (pitch 5).
// Compute: thread = (node in tile, output quad); weights warp-uniform broadcast.
__global__ __launch_bounds__(256)
void fc_kernel(const float* __restrict__ ufc_w, const float* __restrict__ ufc_b,
               const float* __restrict__ ifc_w, const float* __restrict__ ifc_b,
               float* __restrict__ out) {
    __shared__ float4 sW[DO * 4];    // weight row o at sW[o*4 + i]
    __shared__ float  sB[DO];
    __shared__ float4 sM[64 * 5];    // node msg, pitch 5 float4 (bank spread)

    int side = blockIdx.y;
    int tid = threadIdx.x;
    int n0 = blockIdx.x * 64;

    {
        const float4* W4 = reinterpret_cast<const float4*>(side ? ifc_w : ufc_w);
        const float*  B  = side ? ifc_b : ufc_b;
        if (tid < DO * 4) sW[tid] = W4[tid];
        if (tid < DO) sB[tid] = B[tid];
    }
    // stage msgs: 64 nodes x 4 float4, coalesced; leaky once per element
    {
        int node = tid >> 2, i = tid & 3;
        int n = n0 + node;
        const float4* msrc = reinterpret_cast<const float4*>(side ? g_item_msg : g_user_msg);
        float4 m = make_float4(0.f, 0.f, 0.f, 0.f);
        if (n < NN) m = msrc[n * 4 + i];
        m.x = m.x >= 0.f ? m.x : 0.1f * m.x;
        m.y = m.y >= 0.f ? m.y : 0.1f * m.y;
        m.z = m.z >= 0.f ? m.z : 0.1f * m.z;
        m.w = m.w >= 0.f ? m.w : 0.1f * m.w;
        sM[node * 5 + i] = m;
    }
    __syncthreads();

    int node = tid & 63, oq = tid >> 6;   // oq uniform per warp pair; warp-uniform weight reads
    int n = n0 + node;
    if (n >= NN) return;

    float4 m0 = sM[node * 5 + 0], m1 = sM[node * 5 + 1];
    float4 m2 = sM[node * 5 + 2], m3 = sM[node * 5 + 3];

    float4* outp = reinterpret_cast<float4*>(
        out + ((size_t)(side * NN + n)) * DO + oq * 16);
#pragma unroll
    for (int ob = 0; ob < 4; ob++) {
        float4 ov;
        int o0 = oq * 16 + 4 * ob;
        ov.x = sB[o0+0] + dot4(m0, sW[(o0+0)*4+0]) + dot4(m1, sW[(o0+0)*4+1])
                        + dot4(m2, sW[(o0+0)*4+2]) + dot4(m3, sW[(o0+0)*4+3]);
        ov.y = sB[o0+1] + dot4(m0, sW[(o0+1)*4+0]) + dot4(m1, sW[(o0+1)*4+1])
                        + dot4(m2, sW[(o0+1)*4+2]) + dot4(m3, sW[(o0+1)*4+3]);
        ov.z = sB[o0+2] + dot4(m0, sW[(o0+2)*4+0]) + dot4(m1, sW[(o0+2)*4+1])
                        + dot4(m2, sW[(o0+2)*4+2]) + dot4(m3, sW[(o0+2)*4+3]);
        ov.w = sB[o0+3] + dot4(m0, sW[(o0+3)*4+0]) + dot4(m1, sW[(o0+3)*4+1])
                        + dot4(m2, sW[(o0+3)*4+2]) + dot4(m3, sW[(o0+3)*4+3]);
        outp[ob] = ov;
    }
}

// ---------------- launch ----------------
extern "C" void kernel_launch(void* const* d_in, const int* in_sizes, int n_in,
                              void* d_out, int out_size) {
    const float* user_h      = (const float*)d_in[0];
    const float* item_h      = (const float*)d_in[1];
    const float* user_hsum   = (const float*)d_in[2];
    const float* item_hsum   = (const float*)d_in[3];
    const float* review_feat = (const float*)d_in[4];
    const float* prototypes  = (const float*)d_in[5];
    const float* eta         = (const float*)d_in[6];
    const float* node_w_fwd  = (const float*)d_in[7];
    const float* review_w_fwd= (const float*)d_in[8];
    const float* node_w_rev  = (const float*)d_in[9];
    const float* review_w_rev= (const float*)d_in[10];
    const float* ufc_w       = (const float*)d_in[11];
    const float* ufc_b       = (const float*)d_in[12];
    const float* ifc_w       = (const float*)d_in[13];
    const float* ifc_b       = (const float*)d_in[14];
    const int*   edge_src    = (const int*)d_in[15];
    const int*   edge_dst    = (const int*)d_in[16];
    const int*   kptr        = (const int*)d_in[17];

    float* out = (float*)d_out;
    float* out_int = out + (size_t)2 * NN * DO;   // int_dist after ufeat+ifeat

    // launch 1: proj both sides (+ zeroing)
    dim3 gp((R * NN + 255) / 256, 2);
    proj_kernel<<<gp, 256>>>(user_h, item_h, node_w_fwd, node_w_rev, kptr);

    // launch 2: blend-lite
    dim3 gb((E + 31) / 32, R);   // 32 edges per 256-thread block
    blend_kernel<<<gb, 256>>>(user_h, item_h, user_hsum, item_hsum,
                              review_feat, prototypes, eta,
                              edge_src, edge_dst, kptr);

    // launch 3: fused GEMM + scatter (packed f32x2)
    dim3 gg((E + TILE_E - 1) / TILE_E, R);
    gemm_scatter_kernel<<<gg, 256>>>(review_feat, review_w_fwd, review_w_rev,
                                     edge_src, edge_dst, kptr, out_int);

    // launch 4: tiled FC
    dim3 gf((NN + 63) / 64, 2);
    fc_kernel<<<gf, 256>>>(ufc_w, ufc_b, ifc_w, ifc_b, out);
}